// round 1
// baseline (speedup 1.0000x reference)
#include <cuda_runtime.h>
#include <cuda_bf16.h>
#include <math.h>

// ---------------------------------------------------------------------------
// StandardAttention: out = MHA(x; Wq,Wk,Wv,Wo, biases)
// B=2, S=2048, D=1024, H=16, Dh=64. fp32 in/out.
// R0 baseline: fp32 SGEMM projections + flash-attention smem kernel.
// ---------------------------------------------------------------------------

#define BATCH 2
#define SEQ   2048
#define DMODEL 1024
#define NHEADS 16
#define HDIM  64
#define MROWS (BATCH * SEQ)   // 4096

// Scratch (allocation-free rule: use __device__ globals)
__device__ float g_q[MROWS * DMODEL];
__device__ float g_k[MROWS * DMODEL];
__device__ float g_v[MROWS * DMODEL];
__device__ float g_attn[MROWS * DMODEL];

// ---------------------------------------------------------------------------
// SGEMM: C[M,N] = A[M,K] @ W[N,K]^T + bias[N]   (torch Linear convention)
// BM=BN=128, BK=8, 256 threads, 8x8 microtile per thread.
// ---------------------------------------------------------------------------
#define GBM 128
#define GBN 128
#define GBK 8

__global__ __launch_bounds__(256, 2)
void gemm_xwT_kernel(const float* __restrict__ A, const float* __restrict__ W,
                     const float* __restrict__ bias, float* __restrict__ C,
                     int M, int N, int K)
{
    __shared__ float As[GBK][GBM];
    __shared__ float Bs[GBK][GBN];

    const int tid = threadIdx.x;
    const int bm = blockIdx.y * GBM;
    const int bn = blockIdx.x * GBN;

    const int lr = tid >> 1;          // 0..127 (row within tile)
    const int lc = (tid & 1) * 4;     // 0 or 4 (k offset)

    const int ty = tid >> 4;          // 0..15
    const int tx = tid & 15;          // 0..15

    float acc[8][8];
#pragma unroll
    for (int i = 0; i < 8; i++)
#pragma unroll
        for (int j = 0; j < 8; j++) acc[i][j] = 0.0f;

    for (int k0 = 0; k0 < K; k0 += GBK) {
        // Load A tile (128 rows x 8 k) transposed into As[k][m]
        float4 av = *(const float4*)&A[(size_t)(bm + lr) * K + k0 + lc];
        As[lc + 0][lr] = av.x;
        As[lc + 1][lr] = av.y;
        As[lc + 2][lr] = av.z;
        As[lc + 3][lr] = av.w;
        // Load W tile (128 n-rows x 8 k) transposed into Bs[k][n]
        float4 wv = *(const float4*)&W[(size_t)(bn + lr) * K + k0 + lc];
        Bs[lc + 0][lr] = wv.x;
        Bs[lc + 1][lr] = wv.y;
        Bs[lc + 2][lr] = wv.z;
        Bs[lc + 3][lr] = wv.w;
        __syncthreads();

#pragma unroll
        for (int k = 0; k < GBK; k++) {
            float a[8], b[8];
#pragma unroll
            for (int i = 0; i < 8; i++) a[i] = As[k][ty * 8 + i];
#pragma unroll
            for (int j = 0; j < 8; j++) b[j] = Bs[k][tx * 8 + j];
#pragma unroll
            for (int i = 0; i < 8; i++)
#pragma unroll
                for (int j = 0; j < 8; j++)
                    acc[i][j] = fmaf(a[i], b[j], acc[i][j]);
        }
        __syncthreads();
    }

#pragma unroll
    for (int i = 0; i < 8; i++) {
        int m = bm + ty * 8 + i;
#pragma unroll
        for (int j = 0; j < 8; j++) {
            int n = bn + tx * 8 + j;
            C[(size_t)m * N + n] = acc[i][j] + bias[n];
        }
    }
}

// ---------------------------------------------------------------------------
// Flash attention (fp32, online softmax). BQ=BKV=64, Dh=64, 256 threads.
// smem: Q, K, V, S(P), O tiles [64][65] + m/l/corr stats.
// grid: (S/64, H, B)
// ---------------------------------------------------------------------------
#define AQ 64
#define AKV 64
#define ALD 65   // padded leading dim

__global__ __launch_bounds__(256, 2)
void attn_kernel(const float* __restrict__ Q, const float* __restrict__ K,
                 const float* __restrict__ V, float* __restrict__ Out)
{
    extern __shared__ float sm[];
    float* sQ = sm;                  // 64*65
    float* sK = sQ + AQ * ALD;       // 64*65
    float* sV = sK + AKV * ALD;      // 64*65
    float* sS = sV + AKV * ALD;      // 64*65
    float* sO = sS + AQ * ALD;       // 64*65
    float* mrow = sO + AQ * ALD;     // 64
    float* lrow = mrow + AQ;         // 64
    float* crow = lrow + AQ;         // 64

    const int tid = threadIdx.x;
    const int b  = blockIdx.z;
    const int h  = blockIdx.y;
    const int q0 = blockIdx.x * AQ;

    const float* Qb = Q + ((size_t)b * SEQ + q0) * DMODEL + h * HDIM;
    const float* Kb = K + (size_t)b * SEQ * DMODEL + h * HDIM;
    const float* Vb = V + (size_t)b * SEQ * DMODEL + h * HDIM;

    // Load Q tile: 64x64 floats = 1024 float4, 4 per thread
    for (int i = tid; i < AQ * (HDIM / 4); i += 256) {
        int r = i >> 4, c4 = (i & 15) * 4;
        float4 v = *(const float4*)&Qb[(size_t)r * DMODEL + c4];
        sQ[r * ALD + c4 + 0] = v.x;
        sQ[r * ALD + c4 + 1] = v.y;
        sQ[r * ALD + c4 + 2] = v.z;
        sQ[r * ALD + c4 + 3] = v.w;
    }
    // Init O accumulator + stats
    for (int i = tid; i < AQ * HDIM; i += 256) {
        int r = i >> 6, d = i & 63;
        sO[r * ALD + d] = 0.0f;
    }
    if (tid < AQ) { mrow[tid] = -1e30f; lrow[tid] = 0.0f; }
    __syncthreads();

    const float scale = 0.125f;  // 1/sqrt(64)

    for (int kt = 0; kt < SEQ / AKV; kt++) {
        const float* Kt = Kb + (size_t)kt * AKV * DMODEL;
        const float* Vt = Vb + (size_t)kt * AKV * DMODEL;
        // Load K & V tiles: each 1024 float4
        for (int i = tid; i < AKV * (HDIM / 4); i += 256) {
            int r = i >> 4, c4 = (i & 15) * 4;
            float4 kv = *(const float4*)&Kt[(size_t)r * DMODEL + c4];
            sK[r * ALD + c4 + 0] = kv.x;
            sK[r * ALD + c4 + 1] = kv.y;
            sK[r * ALD + c4 + 2] = kv.z;
            sK[r * ALD + c4 + 3] = kv.w;
            float4 vv = *(const float4*)&Vt[(size_t)r * DMODEL + c4];
            sV[r * ALD + c4 + 0] = vv.x;
            sV[r * ALD + c4 + 1] = vv.y;
            sV[r * ALD + c4 + 2] = vv.z;
            sV[r * ALD + c4 + 3] = vv.w;
        }
        __syncthreads();

        // S = scale * Q K^T  (each thread: 16 elements)
        for (int i = tid; i < AQ * AKV; i += 256) {
            int r = i >> 6, c = i & 63;
            float a = 0.0f;
            const float* qr = &sQ[r * ALD];
            const float* kc = &sK[c * ALD];
#pragma unroll
            for (int k = 0; k < HDIM; k++) a = fmaf(qr[k], kc[k], a);
            sS[r * ALD + c] = a * scale;
        }
        __syncthreads();

        // Online softmax row statistics (threads 0..63, one row each)
        if (tid < AQ) {
            int r = tid;
            float mx = mrow[r];
#pragma unroll 8
            for (int c = 0; c < AKV; c++) mx = fmaxf(mx, sS[r * ALD + c]);
            float co = __expf(mrow[r] - mx);
            float sum = 0.0f;
#pragma unroll 8
            for (int c = 0; c < AKV; c++) {
                float p = __expf(sS[r * ALD + c] - mx);
                sS[r * ALD + c] = p;
                sum += p;
            }
            mrow[r] = mx;
            lrow[r] = lrow[r] * co + sum;
            crow[r] = co;
        }
        __syncthreads();

        // O = O*corr + P @ V  (each thread: 16 output elements)
        for (int i = tid; i < AQ * HDIM; i += 256) {
            int r = i >> 6, d = i & 63;
            float a = sO[r * ALD + d] * crow[r];
            const float* pr = &sS[r * ALD];
#pragma unroll
            for (int k = 0; k < AKV; k++) a = fmaf(pr[k], sV[k * ALD + d], a);
            sO[r * ALD + d] = a;
        }
        __syncthreads();
    }

    // Normalize + write out
    for (int i = tid; i < AQ * HDIM; i += 256) {
        int r = i >> 6, d = i & 63;
        Out[((size_t)b * SEQ + q0 + r) * DMODEL + h * HDIM + d] =
            sO[r * ALD + d] / lrow[r];
    }
}

// ---------------------------------------------------------------------------
// Launch
// ---------------------------------------------------------------------------
extern "C" void kernel_launch(void* const* d_in, const int* in_sizes, int n_in,
                              void* d_out, int out_size)
{
    const float* x  = (const float*)d_in[0];
    const float* Wq = (const float*)d_in[1];
    const float* bq = (const float*)d_in[2];
    const float* Wk = (const float*)d_in[3];
    const float* bk = (const float*)d_in[4];
    const float* Wv = (const float*)d_in[5];
    const float* bv = (const float*)d_in[6];
    const float* Wo = (const float*)d_in[7];
    const float* bo = (const float*)d_in[8];
    float* out = (float*)d_out;

    float *q, *k, *v, *attn;
    cudaGetSymbolAddress((void**)&q,    g_q);
    cudaGetSymbolAddress((void**)&k,    g_k);
    cudaGetSymbolAddress((void**)&v,    g_v);
    cudaGetSymbolAddress((void**)&attn, g_attn);

    dim3 gblk(256);
    dim3 ggrid(DMODEL / GBN, MROWS / GBM);  // (8, 32)

    gemm_xwT_kernel<<<ggrid, gblk>>>(x, Wq, bq, q, MROWS, DMODEL, DMODEL);
    gemm_xwT_kernel<<<ggrid, gblk>>>(x, Wk, bk, k, MROWS, DMODEL, DMODEL);
    gemm_xwT_kernel<<<ggrid, gblk>>>(x, Wv, bv, v, MROWS, DMODEL, DMODEL);

    const int smem_bytes = (5 * AQ * ALD + 3 * AQ) * sizeof(float);  // ~84 KB
    static int attr_done = 0;
    cudaFuncSetAttribute(attn_kernel,
                         cudaFuncAttributeMaxDynamicSharedMemorySize, smem_bytes);
    (void)attr_done;

    dim3 agrid(SEQ / AQ, NHEADS, BATCH);  // (32, 16, 2)
    attn_kernel<<<agrid, 256, smem_bytes>>>(q, k, v, attn);

    gemm_xwT_kernel<<<ggrid, gblk>>>(attn, Wo, bo, out, MROWS, DMODEL, DMODEL);
}

// round 3
// speedup vs baseline: 2.0971x; 2.0971x over previous
#include <cuda_runtime.h>
#include <cuda_bf16.h>
#include <cstdint>
#include <math.h>

// ---------------------------------------------------------------------------
// StandardAttention on GB300 (plain sm_103 ptxas target -> mma.sync HMMA path)
// B=2, S=2048, D=1024, H=16, Dh=64, fp32 io.
// R3: mma.sync bf16-split projections + register-tiled fp32 flash attention.
// ---------------------------------------------------------------------------

#define BATCH 2
#define SEQ   2048
#define DMODEL 1024
#define NHEADS 16
#define HDIM  64
#define MROWS (BATCH * SEQ)   // 4096

// ---------------- scratch (__device__ globals; no allocation allowed) ------
__device__ __align__(16) float g_q[MROWS * DMODEL];
__device__ __align__(16) float g_k[MROWS * DMODEL];
__device__ __align__(16) float g_v[MROWS * DMODEL];
__device__ __align__(16) float g_attn[MROWS * DMODEL];

__device__ __align__(16) __nv_bfloat16 g_xhi[MROWS * DMODEL];
__device__ __align__(16) __nv_bfloat16 g_xlo[MROWS * DMODEL];
__device__ __align__(16) __nv_bfloat16 g_ahi[MROWS * DMODEL];
__device__ __align__(16) __nv_bfloat16 g_alo[MROWS * DMODEL];
__device__ __align__(16) __nv_bfloat16 g_whi[4][DMODEL * DMODEL];
__device__ __align__(16) __nv_bfloat16 g_wlo[4][DMODEL * DMODEL];

// ---------------------------------------------------------------------------
// fp32 -> (hi, lo) bf16 split conversion
// ---------------------------------------------------------------------------
__global__ void conv_split_kernel(const float* __restrict__ x,
                                  __nv_bfloat16* __restrict__ hi,
                                  __nv_bfloat16* __restrict__ lo, int n4)
{
    int i = blockIdx.x * blockDim.x + threadIdx.x;
    if (i >= n4) return;
    float4 v = ((const float4*)x)[i];
    __nv_bfloat16 h[4], l[4];
    float f[4] = {v.x, v.y, v.z, v.w};
#pragma unroll
    for (int u = 0; u < 4; u++) {
        h[u] = __float2bfloat16(f[u]);
        l[u] = __float2bfloat16(f[u] - __bfloat162float(h[u]));
    }
    ((uint2*)hi)[i] = *(uint2*)h;
    ((uint2*)lo)[i] = *(uint2*)l;
}

// ---------------------------------------------------------------------------
// mma.sync bf16-split GEMM: C[M,N] = A[M,K] @ W[N,K]^T + bias
// CTA tile 128(M) x 64(N), BK=32, 256 threads = 8 warps (4m x 2n),
// warp tile 32x32 = 2 m16-tiles x 4 n8-tiles. 3 split terms into fp32 acc.
// ---------------------------------------------------------------------------
#define SLD 40   // padded smem leading dim (bf16 elems): 80B rows, 16B aligned

__device__ __forceinline__ uint32_t smem_u32(const void* p) {
    uint32_t a;
    asm("{ .reg .u64 t; cvta.to.shared.u64 t, %1; cvt.u32.u64 %0, t; }"
        : "=r"(a) : "l"(p));
    return a;
}

__device__ __forceinline__ void ldsm_x4(uint32_t* r, uint32_t addr) {
    asm volatile("ldmatrix.sync.aligned.m8n8.x4.shared.b16 {%0,%1,%2,%3}, [%4];"
                 : "=r"(r[0]), "=r"(r[1]), "=r"(r[2]), "=r"(r[3]) : "r"(addr));
}

__device__ __forceinline__ void mma16816(float* d, const uint32_t* a,
                                         uint32_t b0, uint32_t b1) {
    asm volatile(
        "mma.sync.aligned.m16n8k16.row.col.f32.bf16.bf16.f32 "
        "{%0,%1,%2,%3}, {%4,%5,%6,%7}, {%8,%9}, {%0,%1,%2,%3};"
        : "+f"(d[0]), "+f"(d[1]), "+f"(d[2]), "+f"(d[3])
        : "r"(a[0]), "r"(a[1]), "r"(a[2]), "r"(a[3]), "r"(b0), "r"(b1));
}

__global__ void __launch_bounds__(256, 2)
hmma_gemm_kernel(const __nv_bfloat16* __restrict__ Ahi,
                 const __nv_bfloat16* __restrict__ Alo,
                 const __nv_bfloat16* __restrict__ Whi,
                 const __nv_bfloat16* __restrict__ Wlo,
                 const float* __restrict__ bias, float* __restrict__ C,
                 int M, int N, int K)
{
    __shared__ __align__(16) __nv_bfloat16 sAh[128][SLD];
    __shared__ __align__(16) __nv_bfloat16 sAl[128][SLD];
    __shared__ __align__(16) __nv_bfloat16 sWh[64][SLD];
    __shared__ __align__(16) __nv_bfloat16 sWl[64][SLD];

    const int tid = threadIdx.x;
    const int wid = tid >> 5;
    const int lane = tid & 31;
    const int warp_m = wid >> 1;      // 0..3
    const int warp_n = wid & 1;       // 0..1
    const int bm = blockIdx.y * 128;
    const int bn = blockIdx.x * 64;

    float acc[2][4][4];
#pragma unroll
    for (int i = 0; i < 2; i++)
#pragma unroll
        for (int j = 0; j < 4; j++)
#pragma unroll
            for (int e = 0; e < 4; e++) acc[i][j][e] = 0.0f;

    // ldmatrix per-lane source coordinates
    const int blk = lane >> 3, rr = lane & 7;
    const int a_m = (blk & 1) * 8 + rr;   // blocks: (m0-7,k0)(m8-15,k0)(m0-7,k8)(m8-15,k8)
    const int a_k = (blk >> 1) * 8;
    const int b_n = (blk >> 1) * 8 + rr;  // blocks: (n0-7,k0)(n0-7,k8)(n8-15,k0)(n8-15,k8)
    const int b_k = (blk & 1) * 8;

    const uint32_t sAh_b = smem_u32(&sAh[0][0]);
    const uint32_t sAl_b = smem_u32(&sAl[0][0]);
    const uint32_t sWh_b = smem_u32(&sWh[0][0]);
    const uint32_t sWl_b = smem_u32(&sWl[0][0]);

    for (int k0 = 0; k0 < K; k0 += 32) {
        // ---- global -> shared ----
#pragma unroll
        for (int c = tid; c < 512; c += 256) {      // A: 128 rows x 4 x 16B
            int row = c >> 2, c16 = c & 3;
            const size_t goff = (size_t)(bm + row) * K + k0 + c16 * 8;
            *(uint4*)&sAh[row][c16 * 8] = *(const uint4*)&Ahi[goff];
            *(uint4*)&sAl[row][c16 * 8] = *(const uint4*)&Alo[goff];
        }
        {                                            // W: 64 rows x 4 x 16B
            int c = tid;
            int row = c >> 2, c16 = c & 3;
            const size_t goff = (size_t)(bn + row) * K + k0 + c16 * 8;
            *(uint4*)&sWh[row][c16 * 8] = *(const uint4*)&Whi[goff];
            *(uint4*)&sWl[row][c16 * 8] = *(const uint4*)&Wlo[goff];
        }
        __syncthreads();

#pragma unroll
        for (int kk = 0; kk < 32; kk += 16) {
            uint32_t ah[2][4], al[2][4], bh[2][4], bl[2][4];
#pragma unroll
            for (int mt = 0; mt < 2; mt++) {
                uint32_t off = (uint32_t)((warp_m * 32 + mt * 16 + a_m) * SLD
                                          + kk + a_k) * 2;
                ldsm_x4(ah[mt], sAh_b + off);
                ldsm_x4(al[mt], sAl_b + off);
            }
#pragma unroll
            for (int nt2 = 0; nt2 < 2; nt2++) {
                uint32_t off = (uint32_t)((warp_n * 32 + nt2 * 16 + b_n) * SLD
                                          + kk + b_k) * 2;
                ldsm_x4(bh[nt2], sWh_b + off);
                ldsm_x4(bl[nt2], sWl_b + off);
            }
#pragma unroll
            for (int mt = 0; mt < 2; mt++)
#pragma unroll
                for (int nt = 0; nt < 4; nt++) {
                    const int n2 = nt >> 1, hf = (nt & 1) * 2;
                    mma16816(acc[mt][nt], ah[mt], bh[n2][hf], bh[n2][hf + 1]);
                    mma16816(acc[mt][nt], ah[mt], bl[n2][hf], bl[n2][hf + 1]);
                    mma16816(acc[mt][nt], al[mt], bh[n2][hf], bh[n2][hf + 1]);
                }
        }
        __syncthreads();
    }

    // ---- epilogue: bias + store ----
    const int g = lane >> 2, tig = lane & 3;
#pragma unroll
    for (int mt = 0; mt < 2; mt++) {
        const int row0 = bm + warp_m * 32 + mt * 16 + g;
#pragma unroll
        for (int nt = 0; nt < 4; nt++) {
            const int n = bn + warp_n * 32 + nt * 8 + tig * 2;
            const float b0 = bias[n], b1 = bias[n + 1];
            float2 lo = make_float2(acc[mt][nt][0] + b0, acc[mt][nt][1] + b1);
            float2 hi = make_float2(acc[mt][nt][2] + b0, acc[mt][nt][3] + b1);
            *(float2*)&C[(size_t)row0 * N + n] = lo;
            *(float2*)&C[(size_t)(row0 + 8) * N + n] = hi;
        }
    }
}

// ---------------------------------------------------------------------------
// Flash attention, fp32, register-tiled 4x4 microtiles. BQ=BKV=64, 256 thr.
// smem: sQt/sKt transposed [d][r], sV natural [k][d], sSt [c][r].
// ---------------------------------------------------------------------------
#define AQ 64
#define ALD 68

__global__ void __launch_bounds__(256, 2)
attn_kernel(const float* __restrict__ Q, const float* __restrict__ K,
            const float* __restrict__ V, float* __restrict__ Out)
{
    extern __shared__ float sm[];
    float* sQt = sm;                   // [64][68] ([d][r])
    float* sKt = sQt + AQ * ALD;       // [64][68] ([d][c])
    float* sV  = sKt + AQ * ALD;       // [64][68] ([k][d])
    float* sSt = sV + AQ * ALD;        // [64][68] ([c][r])
    float* mrow = sSt + AQ * ALD;
    float* lrow = mrow + AQ;
    float* crow = lrow + AQ;

    const int tid = threadIdx.x;
    const int b = blockIdx.z, h = blockIdx.y;
    const int q0 = blockIdx.x * AQ;
    const int r0 = (tid >> 4) * 4;
    const int c0 = (tid & 15) * 4;

    const float* Qb = Q + ((size_t)b * SEQ + q0) * DMODEL + h * HDIM;
    const float* Kb = K + (size_t)b * SEQ * DMODEL + h * HDIM;
    const float* Vb = V + (size_t)b * SEQ * DMODEL + h * HDIM;

    for (int i = tid; i < AQ * 16; i += 256) {
        int r = i >> 4, d4 = (i & 15) * 4;
        float4 v = *(const float4*)&Qb[(size_t)r * DMODEL + d4];
        sQt[(d4 + 0) * ALD + r] = v.x;
        sQt[(d4 + 1) * ALD + r] = v.y;
        sQt[(d4 + 2) * ALD + r] = v.z;
        sQt[(d4 + 3) * ALD + r] = v.w;
    }
    if (tid < AQ) { mrow[tid] = -1e30f; lrow[tid] = 0.0f; }

    float o[4][4];
#pragma unroll
    for (int i = 0; i < 4; i++)
#pragma unroll
        for (int j = 0; j < 4; j++) o[i][j] = 0.0f;

    __syncthreads();
    const float scale = 0.125f;

    for (int kt = 0; kt < SEQ / AQ; kt++) {
        const float* Kt = Kb + (size_t)kt * AQ * DMODEL;
        const float* Vt = Vb + (size_t)kt * AQ * DMODEL;
        for (int i = tid; i < AQ * 16; i += 256) {
            int r = i >> 4, d4 = (i & 15) * 4;
            float4 kv = *(const float4*)&Kt[(size_t)r * DMODEL + d4];
            sKt[(d4 + 0) * ALD + r] = kv.x;
            sKt[(d4 + 1) * ALD + r] = kv.y;
            sKt[(d4 + 2) * ALD + r] = kv.z;
            sKt[(d4 + 3) * ALD + r] = kv.w;
            *(float4*)&sV[r * ALD + d4] = *(const float4*)&Vt[(size_t)r * DMODEL + d4];
        }
        __syncthreads();

        float s[4][4];
#pragma unroll
        for (int i = 0; i < 4; i++)
#pragma unroll
            for (int j = 0; j < 4; j++) s[i][j] = 0.0f;
#pragma unroll 8
        for (int k = 0; k < HDIM; k++) {
            float4 qv = *(const float4*)&sQt[k * ALD + r0];
            float4 kv = *(const float4*)&sKt[k * ALD + c0];
            float qa[4] = {qv.x, qv.y, qv.z, qv.w};
            float ka[4] = {kv.x, kv.y, kv.z, kv.w};
#pragma unroll
            for (int i = 0; i < 4; i++)
#pragma unroll
                for (int j = 0; j < 4; j++)
                    s[i][j] = fmaf(qa[i], ka[j], s[i][j]);
        }
#pragma unroll
        for (int j = 0; j < 4; j++) {
            float4 w = make_float4(s[0][j] * scale, s[1][j] * scale,
                                   s[2][j] * scale, s[3][j] * scale);
            *(float4*)&sSt[(c0 + j) * ALD + r0] = w;
        }
        __syncthreads();

        {
            int r = tid >> 2, p4 = tid & 3;
            float mx = -1e30f;
            for (int c = p4; c < AQ; c += 4) mx = fmaxf(mx, sSt[c * ALD + r]);
            mx = fmaxf(mx, __shfl_xor_sync(0xffffffffu, mx, 1));
            mx = fmaxf(mx, __shfl_xor_sync(0xffffffffu, mx, 2));
            float mold = mrow[r];
            float mnew = fmaxf(mold, mx);
            float sum = 0.0f;
            for (int c = p4; c < AQ; c += 4) {
                float p = __expf(sSt[c * ALD + r] - mnew);
                sSt[c * ALD + r] = p;
                sum += p;
            }
            sum += __shfl_xor_sync(0xffffffffu, sum, 1);
            sum += __shfl_xor_sync(0xffffffffu, sum, 2);
            if (p4 == 0) {
                float co = __expf(mold - mnew);
                crow[r] = co;
                lrow[r] = lrow[r] * co + sum;
                mrow[r] = mnew;
            }
        }
        __syncthreads();

        float cr[4];
#pragma unroll
        for (int i = 0; i < 4; i++) cr[i] = crow[r0 + i];
#pragma unroll
        for (int i = 0; i < 4; i++)
#pragma unroll
            for (int j = 0; j < 4; j++) o[i][j] *= cr[i];
#pragma unroll 8
        for (int k = 0; k < AQ; k++) {
            float4 pv = *(const float4*)&sSt[k * ALD + r0];
            float4 vv = *(const float4*)&sV[k * ALD + c0];
            float pa[4] = {pv.x, pv.y, pv.z, pv.w};
            float va[4] = {vv.x, vv.y, vv.z, vv.w};
#pragma unroll
            for (int i = 0; i < 4; i++)
#pragma unroll
                for (int j = 0; j < 4; j++)
                    o[i][j] = fmaf(pa[i], va[j], o[i][j]);
        }
        __syncthreads();
    }

#pragma unroll
    for (int i = 0; i < 4; i++) {
        float inv = 1.0f / lrow[r0 + i];
        float4 w = make_float4(o[i][0] * inv, o[i][1] * inv,
                               o[i][2] * inv, o[i][3] * inv);
        *(float4*)&Out[((size_t)b * SEQ + q0 + r0 + i) * DMODEL + h * HDIM + c0] = w;
    }
}

// ---------------------------------------------------------------------------
// Launch
// ---------------------------------------------------------------------------
extern "C" void kernel_launch(void* const* d_in, const int* in_sizes, int n_in,
                              void* d_out, int out_size)
{
    const float* x  = (const float*)d_in[0];
    const float* Wq = (const float*)d_in[1];
    const float* bq = (const float*)d_in[2];
    const float* Wk = (const float*)d_in[3];
    const float* bk = (const float*)d_in[4];
    const float* Wv = (const float*)d_in[5];
    const float* bv = (const float*)d_in[6];
    const float* Wo = (const float*)d_in[7];
    const float* bo = (const float*)d_in[8];
    float* out = (float*)d_out;

    float *q, *k, *v, *attn;
    __nv_bfloat16 *xhi, *xlo, *ahi, *alo, *whi, *wlo;
    cudaGetSymbolAddress((void**)&q, g_q);
    cudaGetSymbolAddress((void**)&k, g_k);
    cudaGetSymbolAddress((void**)&v, g_v);
    cudaGetSymbolAddress((void**)&attn, g_attn);
    cudaGetSymbolAddress((void**)&xhi, g_xhi);
    cudaGetSymbolAddress((void**)&xlo, g_xlo);
    cudaGetSymbolAddress((void**)&ahi, g_ahi);
    cudaGetSymbolAddress((void**)&alo, g_alo);
    cudaGetSymbolAddress((void**)&whi, g_whi);
    cudaGetSymbolAddress((void**)&wlo, g_wlo);

    const int attn_smem = (4 * AQ * ALD + 3 * AQ) * sizeof(float);
    cudaFuncSetAttribute(attn_kernel,
                         cudaFuncAttributeMaxDynamicSharedMemorySize, attn_smem);

    const int nx4 = MROWS * DMODEL / 4;
    const int nw4 = DMODEL * DMODEL / 4;
    conv_split_kernel<<<(nx4 + 255) / 256, 256>>>(x, xhi, xlo, nx4);
    conv_split_kernel<<<(nw4 + 255) / 256, 256>>>(Wq, whi + 0 * DMODEL * DMODEL,
                                                  wlo + 0 * DMODEL * DMODEL, nw4);
    conv_split_kernel<<<(nw4 + 255) / 256, 256>>>(Wk, whi + 1 * DMODEL * DMODEL,
                                                  wlo + 1 * DMODEL * DMODEL, nw4);
    conv_split_kernel<<<(nw4 + 255) / 256, 256>>>(Wv, whi + 2 * DMODEL * DMODEL,
                                                  wlo + 2 * DMODEL * DMODEL, nw4);
    conv_split_kernel<<<(nw4 + 255) / 256, 256>>>(Wo, whi + 3 * DMODEL * DMODEL,
                                                  wlo + 3 * DMODEL * DMODEL, nw4);

    dim3 ggrid(DMODEL / 64, MROWS / 128);  // (16, 32) = 512 CTAs
    hmma_gemm_kernel<<<ggrid, 256>>>(xhi, xlo,
        whi + 0 * DMODEL * DMODEL, wlo + 0 * DMODEL * DMODEL, bq, q,
        MROWS, DMODEL, DMODEL);
    hmma_gemm_kernel<<<ggrid, 256>>>(xhi, xlo,
        whi + 1 * DMODEL * DMODEL, wlo + 1 * DMODEL * DMODEL, bk, k,
        MROWS, DMODEL, DMODEL);
    hmma_gemm_kernel<<<ggrid, 256>>>(xhi, xlo,
        whi + 2 * DMODEL * DMODEL, wlo + 2 * DMODEL * DMODEL, bv, v,
        MROWS, DMODEL, DMODEL);

    dim3 agrid(SEQ / AQ, NHEADS, BATCH);   // (32, 16, 2)
    attn_kernel<<<agrid, 256, attn_smem>>>(q, k, v, attn);

    conv_split_kernel<<<(nx4 + 255) / 256, 256>>>(attn, ahi, alo, nx4);
    hmma_gemm_kernel<<<ggrid, 256>>>(ahi, alo,
        whi + 3 * DMODEL * DMODEL, wlo + 3 * DMODEL * DMODEL, bo, out,
        MROWS, DMODEL, DMODEL);
}

// round 5
// speedup vs baseline: 4.4179x; 2.1067x over previous
#include <cuda_runtime.h>
#include <cuda_bf16.h>
#include <cstdint>
#include <math.h>

// ---------------------------------------------------------------------------
// StandardAttention on GB300 (sm_103 mma.sync HMMA path)
// B=2, S=2048, D=1024, H=16, Dh=64, fp32 io.
// R4: full tensor-core pipeline. Split-bf16 (hi+lo, 3-term) everywhere:
//     projections AND flash-attention QK^T / PV. Fused conversions.
// ---------------------------------------------------------------------------

#define BATCH 2
#define SEQ   2048
#define DMODEL 1024
#define NHEADS 16
#define HDIM  64
#define MROWS (BATCH * SEQ)   // 4096

// ---------------- scratch (__device__ globals) -----------------------------
__device__ __align__(16) __nv_bfloat16 g_xhi[MROWS * DMODEL];
__device__ __align__(16) __nv_bfloat16 g_xlo[MROWS * DMODEL];
__device__ __align__(16) __nv_bfloat16 g_qhi[MROWS * DMODEL];
__device__ __align__(16) __nv_bfloat16 g_qlo[MROWS * DMODEL];
__device__ __align__(16) __nv_bfloat16 g_khi[MROWS * DMODEL];
__device__ __align__(16) __nv_bfloat16 g_klo[MROWS * DMODEL];
__device__ __align__(16) __nv_bfloat16 g_vhi[MROWS * DMODEL];
__device__ __align__(16) __nv_bfloat16 g_vlo[MROWS * DMODEL];
__device__ __align__(16) __nv_bfloat16 g_ahi[MROWS * DMODEL];
__device__ __align__(16) __nv_bfloat16 g_alo[MROWS * DMODEL];
__device__ __align__(16) __nv_bfloat16 g_whi[4][DMODEL * DMODEL];
__device__ __align__(16) __nv_bfloat16 g_wlo[4][DMODEL * DMODEL];

// ---------------- small helpers --------------------------------------------
__device__ __forceinline__ uint32_t smem_u32(const void* p) {
    uint32_t a;
    asm("{ .reg .u64 t; cvta.to.shared.u64 t, %1; cvt.u32.u64 %0, t; }"
        : "=r"(a) : "l"(p));
    return a;
}
__device__ __forceinline__ void ldsm_x4(uint32_t* r, uint32_t addr) {
    asm volatile("ldmatrix.sync.aligned.m8n8.x4.shared.b16 {%0,%1,%2,%3}, [%4];"
                 : "=r"(r[0]), "=r"(r[1]), "=r"(r[2]), "=r"(r[3]) : "r"(addr));
}
__device__ __forceinline__ void ldsm_x4_t(uint32_t* r, uint32_t addr) {
    asm volatile("ldmatrix.sync.aligned.m8n8.x4.trans.shared.b16 {%0,%1,%2,%3}, [%4];"
                 : "=r"(r[0]), "=r"(r[1]), "=r"(r[2]), "=r"(r[3]) : "r"(addr));
}
__device__ __forceinline__ void mma16816(float* d, const uint32_t* a,
                                         uint32_t b0, uint32_t b1) {
    asm volatile(
        "mma.sync.aligned.m16n8k16.row.col.f32.bf16.bf16.f32 "
        "{%0,%1,%2,%3}, {%4,%5,%6,%7}, {%8,%9}, {%0,%1,%2,%3};"
        : "+f"(d[0]), "+f"(d[1]), "+f"(d[2]), "+f"(d[3])
        : "r"(a[0]), "r"(a[1]), "r"(a[2]), "r"(a[3]), "r"(b0), "r"(b1));
}
__device__ __forceinline__ void cp16(uint32_t dst, const void* src) {
    asm volatile("cp.async.cg.shared.global [%0], [%1], 16;"
                 :: "r"(dst), "l"(src) : "memory");
}
#define CP_COMMIT asm volatile("cp.async.commit_group;" ::: "memory")
#define CP_WAIT1  asm volatile("cp.async.wait_group 1;" ::: "memory")
#define CP_WAIT0  asm volatile("cp.async.wait_group 0;" ::: "memory")

// pack two fp32 into split bf16 (hi pair, lo pair), x in low half
__device__ __forceinline__ void split2(float x, float y, uint32_t& h, uint32_t& l) {
    __nv_bfloat16 hx = __float2bfloat16(x), hy = __float2bfloat16(y);
    __nv_bfloat16 lx = __float2bfloat16(x - __bfloat162float(hx));
    __nv_bfloat16 ly = __float2bfloat16(y - __bfloat162float(hy));
    h = ((uint32_t)__bfloat16_as_ushort(hy) << 16) | __bfloat16_as_ushort(hx);
    l = ((uint32_t)__bfloat16_as_ushort(ly) << 16) | __bfloat16_as_ushort(lx);
}

// ---------------------------------------------------------------------------
// fp32 -> (hi, lo) bf16 split conversion (inputs & weights only)
// ---------------------------------------------------------------------------
__global__ void conv_split_kernel(const float* __restrict__ x,
                                  __nv_bfloat16* __restrict__ hi,
                                  __nv_bfloat16* __restrict__ lo, int n4)
{
    int i = blockIdx.x * blockDim.x + threadIdx.x;
    if (i >= n4) return;
    float4 v = ((const float4*)x)[i];
    uint32_t h0, l0, h1, l1;
    split2(v.x, v.y, h0, l0);
    split2(v.z, v.w, h1, l1);
    ((uint2*)hi)[i] = make_uint2(h0, h1);
    ((uint2*)lo)[i] = make_uint2(l0, l1);
}

// ---------------------------------------------------------------------------
// mma.sync bf16-split GEMM: C = A @ W^T + bias.  128x64 CTA tile, BK=32,
// 256 thr = 8 warps (4m x 2n). Epilogue: fp32 (Cf) or split-bf16 (Chi/Clo).
// ---------------------------------------------------------------------------
#define SLD 40

__global__ void __launch_bounds__(256, 2)
hmma_gemm_kernel(const __nv_bfloat16* __restrict__ Ahi,
                 const __nv_bfloat16* __restrict__ Alo,
                 const __nv_bfloat16* __restrict__ Whi,
                 const __nv_bfloat16* __restrict__ Wlo,
                 const float* __restrict__ bias,
                 float* __restrict__ Cf,
                 __nv_bfloat16* __restrict__ Chi,
                 __nv_bfloat16* __restrict__ Clo,
                 int M, int N, int K)
{
    __shared__ __align__(16) __nv_bfloat16 sAh[128][SLD];
    __shared__ __align__(16) __nv_bfloat16 sAl[128][SLD];
    __shared__ __align__(16) __nv_bfloat16 sWh[64][SLD];
    __shared__ __align__(16) __nv_bfloat16 sWl[64][SLD];

    const int tid = threadIdx.x;
    const int wid = tid >> 5;
    const int lane = tid & 31;
    const int warp_m = wid >> 1, warp_n = wid & 1;
    const int bm = blockIdx.y * 128;
    const int bn = blockIdx.x * 64;

    float acc[2][4][4];
#pragma unroll
    for (int i = 0; i < 2; i++)
#pragma unroll
        for (int j = 0; j < 4; j++)
#pragma unroll
            for (int e = 0; e < 4; e++) acc[i][j][e] = 0.0f;

    const int blk = lane >> 3, rr = lane & 7;
    const int a_m = (blk & 1) * 8 + rr, a_k = (blk >> 1) * 8;
    const int b_n = (blk >> 1) * 8 + rr, b_k = (blk & 1) * 8;

    const uint32_t sAh_b = smem_u32(&sAh[0][0]);
    const uint32_t sAl_b = smem_u32(&sAl[0][0]);
    const uint32_t sWh_b = smem_u32(&sWh[0][0]);
    const uint32_t sWl_b = smem_u32(&sWl[0][0]);

    // prefetch coordinates
    const int rA0 = tid >> 2, cA = (tid & 3);          // A slot 0: rows 0..63? (tid>>2: 0..63)
    const int rA1 = rA0 + 64;                          // A slot 1
    const int rW = tid >> 2, cW = (tid & 3);           // W slot (rows 0..63)

    uint4 pAh0, pAl0, pAh1, pAl1, pWh, pWl;
    {
        const size_t g0 = (size_t)(bm + rA0) * K + cA * 8;
        const size_t g1 = (size_t)(bm + rA1) * K + cA * 8;
        const size_t gw = (size_t)(bn + rW) * K + cW * 8;
        pAh0 = *(const uint4*)&Ahi[g0]; pAl0 = *(const uint4*)&Alo[g0];
        pAh1 = *(const uint4*)&Ahi[g1]; pAl1 = *(const uint4*)&Alo[g1];
        pWh  = *(const uint4*)&Whi[gw]; pWl  = *(const uint4*)&Wlo[gw];
    }

    const int nchunks = K / 32;
    for (int kc = 0; kc < nchunks; kc++) {
        *(uint4*)&sAh[rA0][cA * 8] = pAh0; *(uint4*)&sAl[rA0][cA * 8] = pAl0;
        *(uint4*)&sAh[rA1][cA * 8] = pAh1; *(uint4*)&sAl[rA1][cA * 8] = pAl1;
        *(uint4*)&sWh[rW][cW * 8] = pWh;   *(uint4*)&sWl[rW][cW * 8] = pWl;
        __syncthreads();

        if (kc + 1 < nchunks) {
            const int k0 = (kc + 1) * 32;
            const size_t g0 = (size_t)(bm + rA0) * K + k0 + cA * 8;
            const size_t g1 = (size_t)(bm + rA1) * K + k0 + cA * 8;
            const size_t gw = (size_t)(bn + rW) * K + k0 + cW * 8;
            pAh0 = *(const uint4*)&Ahi[g0]; pAl0 = *(const uint4*)&Alo[g0];
            pAh1 = *(const uint4*)&Ahi[g1]; pAl1 = *(const uint4*)&Alo[g1];
            pWh  = *(const uint4*)&Whi[gw]; pWl  = *(const uint4*)&Wlo[gw];
        }

#pragma unroll
        for (int kk = 0; kk < 32; kk += 16) {
            uint32_t ah[2][4], al[2][4], bh[2][4], bl[2][4];
#pragma unroll
            for (int mt = 0; mt < 2; mt++) {
                uint32_t off = (uint32_t)((warp_m * 32 + mt * 16 + a_m) * SLD
                                          + kk + a_k) * 2;
                ldsm_x4(ah[mt], sAh_b + off);
                ldsm_x4(al[mt], sAl_b + off);
            }
#pragma unroll
            for (int nt2 = 0; nt2 < 2; nt2++) {
                uint32_t off = (uint32_t)((warp_n * 32 + nt2 * 16 + b_n) * SLD
                                          + kk + b_k) * 2;
                ldsm_x4(bh[nt2], sWh_b + off);
                ldsm_x4(bl[nt2], sWl_b + off);
            }
#pragma unroll
            for (int mt = 0; mt < 2; mt++)
#pragma unroll
                for (int nt = 0; nt < 4; nt++) {
                    const int n2 = nt >> 1, hf = (nt & 1) * 2;
                    mma16816(acc[mt][nt], ah[mt], bh[n2][hf], bh[n2][hf + 1]);
                    mma16816(acc[mt][nt], ah[mt], bl[n2][hf], bl[n2][hf + 1]);
                    mma16816(acc[mt][nt], al[mt], bh[n2][hf], bh[n2][hf + 1]);
                }
        }
        __syncthreads();
    }

    const int g = lane >> 2, tig = lane & 3;
#pragma unroll
    for (int mt = 0; mt < 2; mt++) {
        const int row0 = bm + warp_m * 32 + mt * 16 + g;
#pragma unroll
        for (int nt = 0; nt < 4; nt++) {
            const int n = bn + warp_n * 32 + nt * 8 + tig * 2;
            const float b0 = bias[n], b1 = bias[n + 1];
            float c0 = acc[mt][nt][0] + b0, c1 = acc[mt][nt][1] + b1;
            float c2 = acc[mt][nt][2] + b0, c3 = acc[mt][nt][3] + b1;
            if (Cf) {
                *(float2*)&Cf[(size_t)row0 * N + n] = make_float2(c0, c1);
                *(float2*)&Cf[(size_t)(row0 + 8) * N + n] = make_float2(c2, c3);
            } else {
                uint32_t h, l;
                split2(c0, c1, h, l);
                *(uint32_t*)&Chi[(size_t)row0 * N + n] = h;
                *(uint32_t*)&Clo[(size_t)row0 * N + n] = l;
                split2(c2, c3, h, l);
                *(uint32_t*)&Chi[(size_t)(row0 + 8) * N + n] = h;
                *(uint32_t*)&Clo[(size_t)(row0 + 8) * N + n] = l;
            }
        }
    }
}

// ---------------------------------------------------------------------------
// Tensor-core flash attention. BQ=64 per CTA (4 warps x 16 rows), BKV=64,
// Dh=64. Split-bf16 3-term for QK^T and PV, fp32 softmax, cp.async double
// buffer on K/V tiles. grid (S/64, H, B), 128 threads.
// ---------------------------------------------------------------------------
#define SLD2 72
#define ATILE (64 * SLD2 * 2)     // 9216 B per tile
#define ABUF  (4 * ATILE)         // Kh,Kl,Vh,Vl = 36864 B per stage
#define ASMEM (2 * ABUF)          // 73728 B

__global__ void __launch_bounds__(128, 2)
attn_mma_kernel(const __nv_bfloat16* __restrict__ qhi,
                const __nv_bfloat16* __restrict__ qlo,
                const __nv_bfloat16* __restrict__ khi,
                const __nv_bfloat16* __restrict__ klo,
                const __nv_bfloat16* __restrict__ vhi,
                const __nv_bfloat16* __restrict__ vlo,
                __nv_bfloat16* __restrict__ ahi,
                __nv_bfloat16* __restrict__ alo)
{
    extern __shared__ char smem[];
    const uint32_t sb = smem_u32(smem);

    const int tid = threadIdx.x;
    const int wid = tid >> 5;
    const int lane = tid & 31;
    const int b = blockIdx.z, h = blockIdx.y;
    const int q0 = blockIdx.x * 64;
    const size_t tokb = (size_t)b * SEQ;

    const int g = lane >> 2, tig = lane & 3;
    const int blk = lane >> 3, rr = lane & 7;
    const int a_m = (blk & 1) * 8 + rr, a_k = (blk >> 1) * 8;
    const int b_n = (blk >> 1) * 8 + rr, b_k = (blk & 1) * 8;

    // ---- stage Q tile into buf0 Kh/Kl regions, build persistent Q frags ----
#pragma unroll
    for (int i = 0; i < 4; i++) {
        int slot = tid + 128 * i;
        int row = slot >> 3, c = slot & 7;
        size_t go = (tokb + q0 + row) * DMODEL + h * HDIM + c * 8;
        *(uint4*)(smem + 0 * ATILE + row * (SLD2 * 2) + c * 16) =
            *(const uint4*)(qhi + go);
        *(uint4*)(smem + 1 * ATILE + row * (SLD2 * 2) + c * 16) =
            *(const uint4*)(qlo + go);
    }
    __syncthreads();

    uint32_t qh[4][4], ql[4][4];
#pragma unroll
    for (int kk = 0; kk < 4; kk++) {
        uint32_t off = (uint32_t)((wid * 16 + a_m) * SLD2 + kk * 16 + a_k) * 2;
        ldsm_x4(qh[kk], sb + 0 * ATILE + off);
        ldsm_x4(ql[kk], sb + 1 * ATILE + off);
    }
    __syncthreads();

    // ---- persistent state ----
    float oacc[8][4];
#pragma unroll
    for (int t = 0; t < 8; t++)
#pragma unroll
        for (int e = 0; e < 4; e++) oacc[t][e] = 0.0f;
    float mst0 = -1e30f, mst1 = -1e30f, lst0 = 0.0f, lst1 = 0.0f;

    // ---- cp.async tile pipeline ----
    const __nv_bfloat16* kvp[4] = {khi, klo, vhi, vlo};
#define ISSUE_TILES(buf, kv0)                                                 \
    do {                                                                      \
        _Pragma("unroll")                                                     \
        for (int i = 0; i < 4; i++) {                                         \
            int slot = tid + 128 * i;                                         \
            int row = slot >> 3, c = slot & 7;                                \
            size_t go = (tokb + (kv0) + row) * DMODEL + h * HDIM + c * 8;     \
            uint32_t so = sb + (buf) * ABUF + row * (SLD2 * 2) + c * 16;      \
            cp16(so + 0 * ATILE, kvp[0] + go);                                \
            cp16(so + 1 * ATILE, kvp[1] + go);                                \
            cp16(so + 2 * ATILE, kvp[2] + go);                                \
            cp16(so + 3 * ATILE, kvp[3] + go);                                \
        }                                                                     \
    } while (0)

    ISSUE_TILES(0, 0);
    CP_COMMIT;

    for (int kt = 0; kt < SEQ / 64; kt++) {
        if (kt + 1 < SEQ / 64) {
            ISSUE_TILES((kt + 1) & 1, (kt + 1) * 64);
            CP_COMMIT;
            CP_WAIT1;
        } else {
            CP_WAIT0;
        }
        __syncthreads();

        const uint32_t base = sb + (kt & 1) * ABUF;

        // ---- S = Q K^T (3-term split) ----
        float sacc[8][4];
#pragma unroll
        for (int t = 0; t < 8; t++)
#pragma unroll
            for (int e = 0; e < 4; e++) sacc[t][e] = 0.0f;

#pragma unroll
        for (int kk = 0; kk < 4; kk++) {
#pragma unroll
            for (int p = 0; p < 4; p++) {
                uint32_t bh[4], bl[4];
                uint32_t off = (uint32_t)((p * 16 + b_n) * SLD2 + kk * 16 + b_k) * 2;
                ldsm_x4(bh, base + 0 * ATILE + off);
                ldsm_x4(bl, base + 1 * ATILE + off);
                mma16816(sacc[2 * p],     qh[kk], bh[0], bh[1]);
                mma16816(sacc[2 * p],     qh[kk], bl[0], bl[1]);
                mma16816(sacc[2 * p],     ql[kk], bh[0], bh[1]);
                mma16816(sacc[2 * p + 1], qh[kk], bh[2], bh[3]);
                mma16816(sacc[2 * p + 1], qh[kk], bl[2], bl[3]);
                mma16816(sacc[2 * p + 1], ql[kk], bh[2], bh[3]);
            }
        }

        // ---- online softmax (rows g and g+8 per lane, quad-reduced) ----
#pragma unroll
        for (int t = 0; t < 8; t++)
#pragma unroll
            for (int e = 0; e < 4; e++) sacc[t][e] *= 0.125f;

        float rm0 = -1e30f, rm1 = -1e30f;
#pragma unroll
        for (int t = 0; t < 8; t++) {
            rm0 = fmaxf(rm0, fmaxf(sacc[t][0], sacc[t][1]));
            rm1 = fmaxf(rm1, fmaxf(sacc[t][2], sacc[t][3]));
        }
        rm0 = fmaxf(rm0, __shfl_xor_sync(0xffffffffu, rm0, 1));
        rm0 = fmaxf(rm0, __shfl_xor_sync(0xffffffffu, rm0, 2));
        rm1 = fmaxf(rm1, __shfl_xor_sync(0xffffffffu, rm1, 1));
        rm1 = fmaxf(rm1, __shfl_xor_sync(0xffffffffu, rm1, 2));

        const float mn0 = fmaxf(mst0, rm0), mn1 = fmaxf(mst1, rm1);
        const float co0 = __expf(mst0 - mn0), co1 = __expf(mst1 - mn1);
        mst0 = mn0; mst1 = mn1;

        float sum0 = 0.0f, sum1 = 0.0f;
#pragma unroll
        for (int t = 0; t < 8; t++) {
            sacc[t][0] = __expf(sacc[t][0] - mn0); sum0 += sacc[t][0];
            sacc[t][1] = __expf(sacc[t][1] - mn0); sum0 += sacc[t][1];
            sacc[t][2] = __expf(sacc[t][2] - mn1); sum1 += sacc[t][2];
            sacc[t][3] = __expf(sacc[t][3] - mn1); sum1 += sacc[t][3];
        }
        sum0 += __shfl_xor_sync(0xffffffffu, sum0, 1);
        sum0 += __shfl_xor_sync(0xffffffffu, sum0, 2);
        sum1 += __shfl_xor_sync(0xffffffffu, sum1, 1);
        sum1 += __shfl_xor_sync(0xffffffffu, sum1, 2);
        lst0 = lst0 * co0 + sum0;
        lst1 = lst1 * co1 + sum1;

#pragma unroll
        for (int t = 0; t < 8; t++) {
            oacc[t][0] *= co0; oacc[t][1] *= co0;
            oacc[t][2] *= co1; oacc[t][3] *= co1;
        }

        // ---- pack P into split-bf16 A fragments (acc layout == A layout) ----
        uint32_t ph[4][4], pl[4][4];
#pragma unroll
        for (int j = 0; j < 4; j++) {
            const int t0 = 2 * j, t1 = 2 * j + 1;
            split2(sacc[t0][0], sacc[t0][1], ph[j][0], pl[j][0]);
            split2(sacc[t0][2], sacc[t0][3], ph[j][1], pl[j][1]);
            split2(sacc[t1][0], sacc[t1][1], ph[j][2], pl[j][2]);
            split2(sacc[t1][2], sacc[t1][3], ph[j][3], pl[j][3]);
        }

        // ---- O += P V (3-term split; V via ldmatrix.trans) ----
#pragma unroll
        for (int kk = 0; kk < 4; kk++) {
#pragma unroll
            for (int p = 0; p < 4; p++) {
                uint32_t bh[4], bl[4];
                uint32_t off = (uint32_t)((kk * 16 + a_m) * SLD2 + p * 16 + a_k) * 2;
                ldsm_x4_t(bh, base + 2 * ATILE + off);
                ldsm_x4_t(bl, base + 3 * ATILE + off);
                mma16816(oacc[2 * p],     ph[kk], bh[0], bh[1]);
                mma16816(oacc[2 * p],     ph[kk], bl[0], bl[1]);
                mma16816(oacc[2 * p],     pl[kk], bh[0], bh[1]);
                mma16816(oacc[2 * p + 1], ph[kk], bh[2], bh[3]);
                mma16816(oacc[2 * p + 1], ph[kk], bl[2], bl[3]);
                mma16816(oacc[2 * p + 1], pl[kk], bh[2], bh[3]);
            }
        }
        __syncthreads();
    }

    // ---- epilogue: normalize, emit split-bf16 for the O-projection ----
    const float inv0 = 1.0f / lst0, inv1 = 1.0f / lst1;
    const size_t base0 = (tokb + q0 + wid * 16 + g) * DMODEL + h * HDIM;
#pragma unroll
    for (int t = 0; t < 8; t++) {
        const int cc = t * 8 + tig * 2;
        uint32_t hh, ll;
        split2(oacc[t][0] * inv0, oacc[t][1] * inv0, hh, ll);
        *(uint32_t*)&ahi[base0 + cc] = hh;
        *(uint32_t*)&alo[base0 + cc] = ll;
        split2(oacc[t][2] * inv1, oacc[t][3] * inv1, hh, ll);
        *(uint32_t*)&ahi[base0 + 8 * DMODEL + cc] = hh;
        *(uint32_t*)&alo[base0 + 8 * DMODEL + cc] = ll;
    }
}

// ---------------------------------------------------------------------------
// Launch
// ---------------------------------------------------------------------------
extern "C" void kernel_launch(void* const* d_in, const int* in_sizes, int n_in,
                              void* d_out, int out_size)
{
    const float* x  = (const float*)d_in[0];
    const float* Wq = (const float*)d_in[1];
    const float* bq = (const float*)d_in[2];
    const float* Wk = (const float*)d_in[3];
    const float* bk = (const float*)d_in[4];
    const float* Wv = (const float*)d_in[5];
    const float* bv = (const float*)d_in[6];
    const float* Wo = (const float*)d_in[7];
    const float* bo = (const float*)d_in[8];
    float* out = (float*)d_out;

    __nv_bfloat16 *xhi, *xlo, *qhi, *qlo, *khi, *klo, *vhi, *vlo, *ahi, *alo;
    __nv_bfloat16 *whi, *wlo;
    cudaGetSymbolAddress((void**)&xhi, g_xhi);
    cudaGetSymbolAddress((void**)&xlo, g_xlo);
    cudaGetSymbolAddress((void**)&qhi, g_qhi);
    cudaGetSymbolAddress((void**)&qlo, g_qlo);
    cudaGetSymbolAddress((void**)&khi, g_khi);
    cudaGetSymbolAddress((void**)&klo, g_klo);
    cudaGetSymbolAddress((void**)&vhi, g_vhi);
    cudaGetSymbolAddress((void**)&vlo, g_vlo);
    cudaGetSymbolAddress((void**)&ahi, g_ahi);
    cudaGetSymbolAddress((void**)&alo, g_alo);
    cudaGetSymbolAddress((void**)&whi, g_whi);
    cudaGetSymbolAddress((void**)&wlo, g_wlo);

    cudaFuncSetAttribute(attn_mma_kernel,
                         cudaFuncAttributeMaxDynamicSharedMemorySize, ASMEM);

    const int nx4 = MROWS * DMODEL / 4;
    const int nw4 = DMODEL * DMODEL / 4;
    const int WSZ = DMODEL * DMODEL;
    conv_split_kernel<<<(nx4 + 255) / 256, 256>>>(x, xhi, xlo, nx4);
    conv_split_kernel<<<(nw4 + 255) / 256, 256>>>(Wq, whi + 0 * WSZ, wlo + 0 * WSZ, nw4);
    conv_split_kernel<<<(nw4 + 255) / 256, 256>>>(Wk, whi + 1 * WSZ, wlo + 1 * WSZ, nw4);
    conv_split_kernel<<<(nw4 + 255) / 256, 256>>>(Wv, whi + 2 * WSZ, wlo + 2 * WSZ, nw4);
    conv_split_kernel<<<(nw4 + 255) / 256, 256>>>(Wo, whi + 3 * WSZ, wlo + 3 * WSZ, nw4);

    dim3 ggrid(DMODEL / 64, MROWS / 128);  // (16, 32)
    hmma_gemm_kernel<<<ggrid, 256>>>(xhi, xlo, whi + 0 * WSZ, wlo + 0 * WSZ,
                                     bq, nullptr, qhi, qlo, MROWS, DMODEL, DMODEL);
    hmma_gemm_kernel<<<ggrid, 256>>>(xhi, xlo, whi + 1 * WSZ, wlo + 1 * WSZ,
                                     bk, nullptr, khi, klo, MROWS, DMODEL, DMODEL);
    hmma_gemm_kernel<<<ggrid, 256>>>(xhi, xlo, whi + 2 * WSZ, wlo + 2 * WSZ,
                                     bv, nullptr, vhi, vlo, MROWS, DMODEL, DMODEL);

    dim3 agrid(SEQ / 64, NHEADS, BATCH);   // (32, 16, 2)
    attn_mma_kernel<<<agrid, 128, ASMEM>>>(qhi, qlo, khi, klo, vhi, vlo, ahi, alo);

    hmma_gemm_kernel<<<ggrid, 256>>>(ahi, alo, whi + 3 * WSZ, wlo + 3 * WSZ,
                                     bo, out, nullptr, nullptr, MROWS, DMODEL, DMODEL);
}

// round 6
// speedup vs baseline: 4.4829x; 1.0147x over previous
#include <cuda_runtime.h>
#include <cuda_bf16.h>
#include <cstdint>
#include <math.h>

// ---------------------------------------------------------------------------
// StandardAttention on GB300 (sm_103 mma.sync HMMA path)
// B=2, S=2048, D=1024, H=16, Dh=64, fp32 io.
// R5: 128x128 cp.async GEMM tiles; BQ=128 attention (halved KV L2 traffic);
//     fused weight conversions. Split-bf16 3-term everywhere.
// ---------------------------------------------------------------------------

#define BATCH 2
#define SEQ   2048
#define DMODEL 1024
#define NHEADS 16
#define HDIM  64
#define MROWS (BATCH * SEQ)   // 4096

// ---------------- scratch (__device__ globals) -----------------------------
__device__ __align__(16) __nv_bfloat16 g_xhi[MROWS * DMODEL];
__device__ __align__(16) __nv_bfloat16 g_xlo[MROWS * DMODEL];
__device__ __align__(16) __nv_bfloat16 g_qhi[MROWS * DMODEL];
__device__ __align__(16) __nv_bfloat16 g_qlo[MROWS * DMODEL];
__device__ __align__(16) __nv_bfloat16 g_khi[MROWS * DMODEL];
__device__ __align__(16) __nv_bfloat16 g_klo[MROWS * DMODEL];
__device__ __align__(16) __nv_bfloat16 g_vhi[MROWS * DMODEL];
__device__ __align__(16) __nv_bfloat16 g_vlo[MROWS * DMODEL];
__device__ __align__(16) __nv_bfloat16 g_ahi[MROWS * DMODEL];
__device__ __align__(16) __nv_bfloat16 g_alo[MROWS * DMODEL];
__device__ __align__(16) __nv_bfloat16 g_whi[4][DMODEL * DMODEL];
__device__ __align__(16) __nv_bfloat16 g_wlo[4][DMODEL * DMODEL];

// ---------------- small helpers --------------------------------------------
__device__ __forceinline__ uint32_t smem_u32(const void* p) {
    uint32_t a;
    asm("{ .reg .u64 t; cvta.to.shared.u64 t, %1; cvt.u32.u64 %0, t; }"
        : "=r"(a) : "l"(p));
    return a;
}
__device__ __forceinline__ void ldsm_x4(uint32_t* r, uint32_t addr) {
    asm volatile("ldmatrix.sync.aligned.m8n8.x4.shared.b16 {%0,%1,%2,%3}, [%4];"
                 : "=r"(r[0]), "=r"(r[1]), "=r"(r[2]), "=r"(r[3]) : "r"(addr));
}
__device__ __forceinline__ void ldsm_x4_t(uint32_t* r, uint32_t addr) {
    asm volatile("ldmatrix.sync.aligned.m8n8.x4.trans.shared.b16 {%0,%1,%2,%3}, [%4];"
                 : "=r"(r[0]), "=r"(r[1]), "=r"(r[2]), "=r"(r[3]) : "r"(addr));
}
__device__ __forceinline__ void mma16816(float* d, const uint32_t* a,
                                         uint32_t b0, uint32_t b1) {
    asm volatile(
        "mma.sync.aligned.m16n8k16.row.col.f32.bf16.bf16.f32 "
        "{%0,%1,%2,%3}, {%4,%5,%6,%7}, {%8,%9}, {%0,%1,%2,%3};"
        : "+f"(d[0]), "+f"(d[1]), "+f"(d[2]), "+f"(d[3])
        : "r"(a[0]), "r"(a[1]), "r"(a[2]), "r"(a[3]), "r"(b0), "r"(b1));
}
__device__ __forceinline__ void cp16(uint32_t dst, const void* src) {
    asm volatile("cp.async.cg.shared.global [%0], [%1], 16;"
                 :: "r"(dst), "l"(src) : "memory");
}
#define CP_COMMIT asm volatile("cp.async.commit_group;" ::: "memory")
#define CP_WAIT1  asm volatile("cp.async.wait_group 1;" ::: "memory")
#define CP_WAIT0  asm volatile("cp.async.wait_group 0;" ::: "memory")

__device__ __forceinline__ void split2(float x, float y, uint32_t& h, uint32_t& l) {
    __nv_bfloat16 hx = __float2bfloat16(x), hy = __float2bfloat16(y);
    __nv_bfloat16 lx = __float2bfloat16(x - __bfloat162float(hx));
    __nv_bfloat16 ly = __float2bfloat16(y - __bfloat162float(hy));
    h = ((uint32_t)__bfloat16_as_ushort(hy) << 16) | __bfloat16_as_ushort(hx);
    l = ((uint32_t)__bfloat16_as_ushort(ly) << 16) | __bfloat16_as_ushort(lx);
}

// ---------------------------------------------------------------------------
// fp32 -> split bf16 conversions
// ---------------------------------------------------------------------------
__global__ void conv_split_kernel(const float* __restrict__ x,
                                  __nv_bfloat16* __restrict__ hi,
                                  __nv_bfloat16* __restrict__ lo, int n4)
{
    int i = blockIdx.x * blockDim.x + threadIdx.x;
    if (i >= n4) return;
    float4 v = ((const float4*)x)[i];
    uint32_t h0, l0, h1, l1;
    split2(v.x, v.y, h0, l0);
    split2(v.z, v.w, h1, l1);
    ((uint2*)hi)[i] = make_uint2(h0, h1);
    ((uint2*)lo)[i] = make_uint2(l0, l1);
}

__global__ void conv_w4_kernel(const float* __restrict__ W0,
                               const float* __restrict__ W1,
                               const float* __restrict__ W2,
                               const float* __restrict__ W3,
                               __nv_bfloat16* __restrict__ hi,
                               __nv_bfloat16* __restrict__ lo, int n4)
{
    int i = blockIdx.x * blockDim.x + threadIdx.x;
    if (i >= n4) return;
    const int w = blockIdx.y;
    const float* src = (w == 0) ? W0 : (w == 1) ? W1 : (w == 2) ? W2 : W3;
    const size_t off = (size_t)w * (DMODEL * (size_t)DMODEL / 4);
    float4 v = ((const float4*)src)[i];
    uint32_t h0, l0, h1, l1;
    split2(v.x, v.y, h0, l0);
    split2(v.z, v.w, h1, l1);
    ((uint2*)hi)[off + i] = make_uint2(h0, h1);
    ((uint2*)lo)[off + i] = make_uint2(l0, l1);
}

// ---------------------------------------------------------------------------
// mma.sync bf16-split GEMM v2: C = A @ W^T + bias.
// 128x128 CTA tile, BK=32, 2-stage cp.async, 256 thr = 8 warps (4m x 2n),
// warp tile 32x64. Epilogue: fp32 (Cf) or split-bf16 (Chi/Clo).
// ---------------------------------------------------------------------------
#define GSLD 40                  // padded row: 40 bf16 = 80 B
#define GT   10240               // bytes per (128 x GSLD) bf16 tile
#define GSTAGE (4 * GT)          // Ah, Al, Wh, Wl
#define GSMEM (2 * GSTAGE)       // 81920 B

__global__ void __launch_bounds__(256, 2)
hmma_gemm_kernel(const __nv_bfloat16* __restrict__ Ahi,
                 const __nv_bfloat16* __restrict__ Alo,
                 const __nv_bfloat16* __restrict__ Whi,
                 const __nv_bfloat16* __restrict__ Wlo,
                 const float* __restrict__ bias,
                 float* __restrict__ Cf,
                 __nv_bfloat16* __restrict__ Chi,
                 __nv_bfloat16* __restrict__ Clo,
                 int M, int N, int K)
{
    extern __shared__ char smg[];
    const uint32_t sb = smem_u32(smg);

    const int tid = threadIdx.x;
    const int wid = tid >> 5;
    const int lane = tid & 31;
    const int warp_m = wid >> 1, warp_n = wid & 1;
    const int bm = blockIdx.y * 128;
    const int bn = blockIdx.x * 128;

    float acc[2][8][4];
#pragma unroll
    for (int i = 0; i < 2; i++)
#pragma unroll
        for (int j = 0; j < 8; j++)
#pragma unroll
            for (int e = 0; e < 4; e++) acc[i][j][e] = 0.0f;

    const int blk = lane >> 3, rr = lane & 7;
    const int a_m = (blk & 1) * 8 + rr, a_k = (blk >> 1) * 8;
    const int b_n = (blk >> 1) * 8 + rr, b_k = (blk & 1) * 8;

    // cp.async coordinates: each thread: row = tid>>1, two 16B chunks
    const int crow = tid >> 1;
    const int cc = (tid & 1) * 2;

#define G_ISSUE(kc, buf)                                                      \
    do {                                                                      \
        const size_t ga = (size_t)(bm + crow) * K + (kc) * 32 + cc * 8;       \
        const size_t gw = (size_t)(bn + crow) * K + (kc) * 32 + cc * 8;       \
        const uint32_t s = sb + (buf) * GSTAGE;                               \
        const uint32_t ro = crow * 80 + cc * 16;                              \
        cp16(s + 0 * GT + ro,      Ahi + ga);                                 \
        cp16(s + 0 * GT + ro + 16, Ahi + ga + 8);                             \
        cp16(s + 1 * GT + ro,      Alo + ga);                                 \
        cp16(s + 1 * GT + ro + 16, Alo + ga + 8);                             \
        cp16(s + 2 * GT + ro,      Whi + gw);                                 \
        cp16(s + 2 * GT + ro + 16, Whi + gw + 8);                             \
        cp16(s + 3 * GT + ro,      Wlo + gw);                                 \
        cp16(s + 3 * GT + ro + 16, Wlo + gw + 8);                             \
    } while (0)

    G_ISSUE(0, 0);
    CP_COMMIT;

    const int nch = K / 32;
    for (int kc = 0; kc < nch; kc++) {
        if (kc + 1 < nch) {
            G_ISSUE(kc + 1, (kc + 1) & 1);
            CP_COMMIT;
            CP_WAIT1;
        } else {
            CP_WAIT0;
        }
        __syncthreads();

        const uint32_t s = sb + (kc & 1) * GSTAGE;
#pragma unroll
        for (int kk = 0; kk < 32; kk += 16) {
            uint32_t ah[2][4], al[2][4];
#pragma unroll
            for (int mt = 0; mt < 2; mt++) {
                uint32_t off = (uint32_t)((warp_m * 32 + mt * 16 + a_m) * GSLD
                                          + kk + a_k) * 2;
                ldsm_x4(ah[mt], s + 0 * GT + off);
                ldsm_x4(al[mt], s + 1 * GT + off);
            }
#pragma unroll
            for (int nt2 = 0; nt2 < 4; nt2++) {
                uint32_t bh[4], bl[4];
                uint32_t off = (uint32_t)((warp_n * 64 + nt2 * 16 + b_n) * GSLD
                                          + kk + b_k) * 2;
                ldsm_x4(bh, s + 2 * GT + off);
                ldsm_x4(bl, s + 3 * GT + off);
#pragma unroll
                for (int mt = 0; mt < 2; mt++)
#pragma unroll
                    for (int hf = 0; hf < 2; hf++) {
                        float* d = acc[mt][nt2 * 2 + hf];
                        mma16816(d, ah[mt], bh[hf * 2], bh[hf * 2 + 1]);
                        mma16816(d, ah[mt], bl[hf * 2], bl[hf * 2 + 1]);
                        mma16816(d, al[mt], bh[hf * 2], bh[hf * 2 + 1]);
                    }
            }
        }
        __syncthreads();
    }

    const int g = lane >> 2, tig = lane & 3;
#pragma unroll
    for (int mt = 0; mt < 2; mt++) {
        const int row0 = bm + warp_m * 32 + mt * 16 + g;
#pragma unroll
        for (int nt = 0; nt < 8; nt++) {
            const int n = bn + warp_n * 64 + nt * 8 + tig * 2;
            const float b0 = bias[n], b1 = bias[n + 1];
            float c0 = acc[mt][nt][0] + b0, c1 = acc[mt][nt][1] + b1;
            float c2 = acc[mt][nt][2] + b0, c3 = acc[mt][nt][3] + b1;
            if (Cf) {
                *(float2*)&Cf[(size_t)row0 * N + n] = make_float2(c0, c1);
                *(float2*)&Cf[(size_t)(row0 + 8) * N + n] = make_float2(c2, c3);
            } else {
                uint32_t h, l;
                split2(c0, c1, h, l);
                *(uint32_t*)&Chi[(size_t)row0 * N + n] = h;
                *(uint32_t*)&Clo[(size_t)row0 * N + n] = l;
                split2(c2, c3, h, l);
                *(uint32_t*)&Chi[(size_t)(row0 + 8) * N + n] = h;
                *(uint32_t*)&Clo[(size_t)(row0 + 8) * N + n] = l;
            }
        }
    }
}

// ---------------------------------------------------------------------------
// Tensor-core flash attention v2. BQ=128 (8 warps x 16 rows), BKV=64, Dh=64.
// Split-bf16 3-term QK^T and PV, fp32 softmax, cp.async double-buffered KV.
// grid (S/128, H, B), 256 threads.
// ---------------------------------------------------------------------------
#define SLD2 72
#define ATILE (64 * SLD2 * 2)     // 9216 B
#define ABUF  (4 * ATILE)         // Kh,Kl,Vh,Vl per stage = 36864 B
#define ASMEM (2 * ABUF)          // 73728 B

__global__ void __launch_bounds__(256, 1)
attn_mma_kernel(const __nv_bfloat16* __restrict__ qhi,
                const __nv_bfloat16* __restrict__ qlo,
                const __nv_bfloat16* __restrict__ khi,
                const __nv_bfloat16* __restrict__ klo,
                const __nv_bfloat16* __restrict__ vhi,
                const __nv_bfloat16* __restrict__ vlo,
                __nv_bfloat16* __restrict__ ahi,
                __nv_bfloat16* __restrict__ alo)
{
    extern __shared__ char smem[];
    const uint32_t sb = smem_u32(smem);

    const int tid = threadIdx.x;
    const int wid = tid >> 5;
    const int lane = tid & 31;
    const int b = blockIdx.z, h = blockIdx.y;
    const int q0 = blockIdx.x * 128;
    const size_t tokb = (size_t)b * SEQ;

    const int g = lane >> 2, tig = lane & 3;
    const int blk = lane >> 3, rr = lane & 7;
    const int a_m = (blk & 1) * 8 + rr, a_k = (blk >> 1) * 8;
    const int b_n = (blk >> 1) * 8 + rr, b_k = (blk & 1) * 8;

    // ---- stage Q tile (128 rows) into buf0: Qhi at 0, Qlo at +2*ATILE ----
#pragma unroll
    for (int i = 0; i < 4; i++) {
        int slot = tid + 256 * i;
        int row = slot >> 3, c = slot & 7;
        size_t go = (tokb + q0 + row) * DMODEL + h * HDIM + c * 8;
        *(uint4*)(smem + row * (SLD2 * 2) + c * 16) = *(const uint4*)(qhi + go);
        *(uint4*)(smem + 2 * ATILE + row * (SLD2 * 2) + c * 16) =
            *(const uint4*)(qlo + go);
    }
    __syncthreads();

    uint32_t qh[4][4], ql[4][4];
#pragma unroll
    for (int kk = 0; kk < 4; kk++) {
        uint32_t off = (uint32_t)((wid * 16 + a_m) * SLD2 + kk * 16 + a_k) * 2;
        ldsm_x4(qh[kk], sb + off);
        ldsm_x4(ql[kk], sb + 2 * ATILE + off);
    }
    __syncthreads();

    float oacc[8][4];
#pragma unroll
    for (int t = 0; t < 8; t++)
#pragma unroll
        for (int e = 0; e < 4; e++) oacc[t][e] = 0.0f;
    float mst0 = -1e30f, mst1 = -1e30f, lst0 = 0.0f, lst1 = 0.0f;

    const __nv_bfloat16* kvp[4] = {khi, klo, vhi, vlo};
#define ISSUE_TILES(buf, kv0)                                                 \
    do {                                                                      \
        _Pragma("unroll")                                                     \
        for (int i = 0; i < 2; i++) {                                         \
            int slot = tid + 256 * i;                                         \
            int row = slot >> 3, c = slot & 7;                                \
            size_t go = (tokb + (kv0) + row) * DMODEL + h * HDIM + c * 8;     \
            uint32_t so = sb + (buf) * ABUF + row * (SLD2 * 2) + c * 16;      \
            cp16(so + 0 * ATILE, kvp[0] + go);                                \
            cp16(so + 1 * ATILE, kvp[1] + go);                                \
            cp16(so + 2 * ATILE, kvp[2] + go);                                \
            cp16(so + 3 * ATILE, kvp[3] + go);                                \
        }                                                                     \
    } while (0)

    ISSUE_TILES(0, 0);
    CP_COMMIT;

    for (int kt = 0; kt < SEQ / 64; kt++) {
        if (kt + 1 < SEQ / 64) {
            ISSUE_TILES((kt + 1) & 1, (kt + 1) * 64);
            CP_COMMIT;
            CP_WAIT1;
        } else {
            CP_WAIT0;
        }
        __syncthreads();

        const uint32_t base = sb + (kt & 1) * ABUF;

        // ---- S = Q K^T (3-term split) ----
        float sacc[8][4];
#pragma unroll
        for (int t = 0; t < 8; t++)
#pragma unroll
            for (int e = 0; e < 4; e++) sacc[t][e] = 0.0f;

#pragma unroll
        for (int kk = 0; kk < 4; kk++) {
#pragma unroll
            for (int p = 0; p < 4; p++) {
                uint32_t bh[4], bl[4];
                uint32_t off = (uint32_t)((p * 16 + b_n) * SLD2 + kk * 16 + b_k) * 2;
                ldsm_x4(bh, base + 0 * ATILE + off);
                ldsm_x4(bl, base + 1 * ATILE + off);
                mma16816(sacc[2 * p],     qh[kk], bh[0], bh[1]);
                mma16816(sacc[2 * p],     qh[kk], bl[0], bl[1]);
                mma16816(sacc[2 * p],     ql[kk], bh[0], bh[1]);
                mma16816(sacc[2 * p + 1], qh[kk], bh[2], bh[3]);
                mma16816(sacc[2 * p + 1], qh[kk], bl[2], bl[3]);
                mma16816(sacc[2 * p + 1], ql[kk], bh[2], bh[3]);
            }
        }

        // ---- online softmax ----
#pragma unroll
        for (int t = 0; t < 8; t++)
#pragma unroll
            for (int e = 0; e < 4; e++) sacc[t][e] *= 0.125f;

        float rm0 = -1e30f, rm1 = -1e30f;
#pragma unroll
        for (int t = 0; t < 8; t++) {
            rm0 = fmaxf(rm0, fmaxf(sacc[t][0], sacc[t][1]));
            rm1 = fmaxf(rm1, fmaxf(sacc[t][2], sacc[t][3]));
        }
        rm0 = fmaxf(rm0, __shfl_xor_sync(0xffffffffu, rm0, 1));
        rm0 = fmaxf(rm0, __shfl_xor_sync(0xffffffffu, rm0, 2));
        rm1 = fmaxf(rm1, __shfl_xor_sync(0xffffffffu, rm1, 1));
        rm1 = fmaxf(rm1, __shfl_xor_sync(0xffffffffu, rm1, 2));

        const float mn0 = fmaxf(mst0, rm0), mn1 = fmaxf(mst1, rm1);
        const float co0 = __expf(mst0 - mn0), co1 = __expf(mst1 - mn1);
        mst0 = mn0; mst1 = mn1;

        float sum0 = 0.0f, sum1 = 0.0f;
#pragma unroll
        for (int t = 0; t < 8; t++) {
            sacc[t][0] = __expf(sacc[t][0] - mn0); sum0 += sacc[t][0];
            sacc[t][1] = __expf(sacc[t][1] - mn0); sum0 += sacc[t][1];
            sacc[t][2] = __expf(sacc[t][2] - mn1); sum1 += sacc[t][2];
            sacc[t][3] = __expf(sacc[t][3] - mn1); sum1 += sacc[t][3];
        }
        sum0 += __shfl_xor_sync(0xffffffffu, sum0, 1);
        sum0 += __shfl_xor_sync(0xffffffffu, sum0, 2);
        sum1 += __shfl_xor_sync(0xffffffffu, sum1, 1);
        sum1 += __shfl_xor_sync(0xffffffffu, sum1, 2);
        lst0 = lst0 * co0 + sum0;
        lst1 = lst1 * co1 + sum1;

#pragma unroll
        for (int t = 0; t < 8; t++) {
            oacc[t][0] *= co0; oacc[t][1] *= co0;
            oacc[t][2] *= co1; oacc[t][3] *= co1;
        }

        // ---- pack P (acc layout == A-fragment layout) ----
        uint32_t ph[4][4], pl[4][4];
#pragma unroll
        for (int j = 0; j < 4; j++) {
            const int t0 = 2 * j, t1 = 2 * j + 1;
            split2(sacc[t0][0], sacc[t0][1], ph[j][0], pl[j][0]);
            split2(sacc[t0][2], sacc[t0][3], ph[j][1], pl[j][1]);
            split2(sacc[t1][0], sacc[t1][1], ph[j][2], pl[j][2]);
            split2(sacc[t1][2], sacc[t1][3], ph[j][3], pl[j][3]);
        }

        // ---- O += P V (3-term split; V via ldmatrix.trans) ----
#pragma unroll
        for (int kk = 0; kk < 4; kk++) {
#pragma unroll
            for (int p = 0; p < 4; p++) {
                uint32_t bh[4], bl[4];
                uint32_t off = (uint32_t)((kk * 16 + a_m) * SLD2 + p * 16 + a_k) * 2;
                ldsm_x4_t(bh, base + 2 * ATILE + off);
                ldsm_x4_t(bl, base + 3 * ATILE + off);
                mma16816(oacc[2 * p],     ph[kk], bh[0], bh[1]);
                mma16816(oacc[2 * p],     ph[kk], bl[0], bl[1]);
                mma16816(oacc[2 * p],     pl[kk], bh[0], bh[1]);
                mma16816(oacc[2 * p + 1], ph[kk], bh[2], bh[3]);
                mma16816(oacc[2 * p + 1], ph[kk], bl[2], bl[3]);
                mma16816(oacc[2 * p + 1], pl[kk], bh[2], bh[3]);
            }
        }
        __syncthreads();
    }

    // ---- epilogue: normalize, emit split-bf16 ----
    const float inv0 = 1.0f / lst0, inv1 = 1.0f / lst1;
    const size_t base0 = (tokb + q0 + wid * 16 + g) * DMODEL + h * HDIM;
#pragma unroll
    for (int t = 0; t < 8; t++) {
        const int cc = t * 8 + tig * 2;
        uint32_t hh, ll;
        split2(oacc[t][0] * inv0, oacc[t][1] * inv0, hh, ll);
        *(uint32_t*)&ahi[base0 + cc] = hh;
        *(uint32_t*)&alo[base0 + cc] = ll;
        split2(oacc[t][2] * inv1, oacc[t][3] * inv1, hh, ll);
        *(uint32_t*)&ahi[base0 + 8 * DMODEL + cc] = hh;
        *(uint32_t*)&alo[base0 + 8 * DMODEL + cc] = ll;
    }
}

// ---------------------------------------------------------------------------
// Launch
// ---------------------------------------------------------------------------
extern "C" void kernel_launch(void* const* d_in, const int* in_sizes, int n_in,
                              void* d_out, int out_size)
{
    const float* x  = (const float*)d_in[0];
    const float* Wq = (const float*)d_in[1];
    const float* bq = (const float*)d_in[2];
    const float* Wk = (const float*)d_in[3];
    const float* bk = (const float*)d_in[4];
    const float* Wv = (const float*)d_in[5];
    const float* bv = (const float*)d_in[6];
    const float* Wo = (const float*)d_in[7];
    const float* bo = (const float*)d_in[8];
    float* out = (float*)d_out;

    __nv_bfloat16 *xhi, *xlo, *qhi, *qlo, *khi, *klo, *vhi, *vlo, *ahi, *alo;
    __nv_bfloat16 *whi, *wlo;
    cudaGetSymbolAddress((void**)&xhi, g_xhi);
    cudaGetSymbolAddress((void**)&xlo, g_xlo);
    cudaGetSymbolAddress((void**)&qhi, g_qhi);
    cudaGetSymbolAddress((void**)&qlo, g_qlo);
    cudaGetSymbolAddress((void**)&khi, g_khi);
    cudaGetSymbolAddress((void**)&klo, g_klo);
    cudaGetSymbolAddress((void**)&vhi, g_vhi);
    cudaGetSymbolAddress((void**)&vlo, g_vlo);
    cudaGetSymbolAddress((void**)&ahi, g_ahi);
    cudaGetSymbolAddress((void**)&alo, g_alo);
    cudaGetSymbolAddress((void**)&whi, g_whi);
    cudaGetSymbolAddress((void**)&wlo, g_wlo);

    cudaFuncSetAttribute(hmma_gemm_kernel,
                         cudaFuncAttributeMaxDynamicSharedMemorySize, GSMEM);
    cudaFuncSetAttribute(attn_mma_kernel,
                         cudaFuncAttributeMaxDynamicSharedMemorySize, ASMEM);

    const int nx4 = MROWS * DMODEL / 4;
    const int nw4 = DMODEL * DMODEL / 4;
    const int WSZ = DMODEL * DMODEL;
    conv_split_kernel<<<(nx4 + 255) / 256, 256>>>(x, xhi, xlo, nx4);
    dim3 wgrid((nw4 + 255) / 256, 4);
    conv_w4_kernel<<<wgrid, 256>>>(Wq, Wk, Wv, Wo, whi, wlo, nw4);

    dim3 ggrid(DMODEL / 128, MROWS / 128);  // (8, 32) = 256 CTAs
    hmma_gemm_kernel<<<ggrid, 256, GSMEM>>>(xhi, xlo, whi + 0 * WSZ, wlo + 0 * WSZ,
                                            bq, nullptr, qhi, qlo, MROWS, DMODEL, DMODEL);
    hmma_gemm_kernel<<<ggrid, 256, GSMEM>>>(xhi, xlo, whi + 1 * WSZ, wlo + 1 * WSZ,
                                            bk, nullptr, khi, klo, MROWS, DMODEL, DMODEL);
    hmma_gemm_kernel<<<ggrid, 256, GSMEM>>>(xhi, xlo, whi + 2 * WSZ, wlo + 2 * WSZ,
                                            bv, nullptr, vhi, vlo, MROWS, DMODEL, DMODEL);

    dim3 agrid(SEQ / 128, NHEADS, BATCH);   // (16, 16, 2) = 512 CTAs
    attn_mma_kernel<<<agrid, 256, ASMEM>>>(qhi, qlo, khi, klo, vhi, vlo, ahi, alo);

    hmma_gemm_kernel<<<ggrid, 256, GSMEM>>>(ahi, alo, whi + 3 * WSZ, wlo + 3 * WSZ,
                                            bo, out, nullptr, nullptr, MROWS, DMODEL, DMODEL);
}

// round 7
// speedup vs baseline: 4.5151x; 1.0072x over previous
#include <cuda_runtime.h>
#include <cuda_bf16.h>
#include <cstdint>
#include <math.h>

// ---------------------------------------------------------------------------
// StandardAttention on GB300 (sm_103 mma.sync HMMA path)
// B=2, S=2048, D=1024, H=16, Dh=64, fp32 io.
// R6: ILP-scheduled GEMM inner loop (term-grouped MMA issue), fused QKV
//     projection (N=3072), single conversion launch. Split-bf16 3-term.
// ---------------------------------------------------------------------------

#define BATCH 2
#define SEQ   2048
#define DMODEL 1024
#define NHEADS 16
#define HDIM  64
#define MROWS (BATCH * SEQ)   // 4096
#define QKVD  (3 * DMODEL)    // 3072

// ---------------- scratch (__device__ globals) -----------------------------
__device__ __align__(16) __nv_bfloat16 g_xhi[MROWS * DMODEL];
__device__ __align__(16) __nv_bfloat16 g_xlo[MROWS * DMODEL];
__device__ __align__(16) __nv_bfloat16 g_qkvhi[MROWS * QKVD];
__device__ __align__(16) __nv_bfloat16 g_qkvlo[MROWS * QKVD];
__device__ __align__(16) __nv_bfloat16 g_ahi[MROWS * DMODEL];
__device__ __align__(16) __nv_bfloat16 g_alo[MROWS * DMODEL];
__device__ __align__(16) __nv_bfloat16 g_whi[4][DMODEL * DMODEL];
__device__ __align__(16) __nv_bfloat16 g_wlo[4][DMODEL * DMODEL];

// ---------------- small helpers --------------------------------------------
__device__ __forceinline__ uint32_t smem_u32(const void* p) {
    uint32_t a;
    asm("{ .reg .u64 t; cvta.to.shared.u64 t, %1; cvt.u32.u64 %0, t; }"
        : "=r"(a) : "l"(p));
    return a;
}
__device__ __forceinline__ void ldsm_x4(uint32_t* r, uint32_t addr) {
    asm volatile("ldmatrix.sync.aligned.m8n8.x4.shared.b16 {%0,%1,%2,%3}, [%4];"
                 : "=r"(r[0]), "=r"(r[1]), "=r"(r[2]), "=r"(r[3]) : "r"(addr));
}
__device__ __forceinline__ void ldsm_x4_t(uint32_t* r, uint32_t addr) {
    asm volatile("ldmatrix.sync.aligned.m8n8.x4.trans.shared.b16 {%0,%1,%2,%3}, [%4];"
                 : "=r"(r[0]), "=r"(r[1]), "=r"(r[2]), "=r"(r[3]) : "r"(addr));
}
__device__ __forceinline__ void mma16816(float* d, const uint32_t* a,
                                         uint32_t b0, uint32_t b1) {
    asm volatile(
        "mma.sync.aligned.m16n8k16.row.col.f32.bf16.bf16.f32 "
        "{%0,%1,%2,%3}, {%4,%5,%6,%7}, {%8,%9}, {%0,%1,%2,%3};"
        : "+f"(d[0]), "+f"(d[1]), "+f"(d[2]), "+f"(d[3])
        : "r"(a[0]), "r"(a[1]), "r"(a[2]), "r"(a[3]), "r"(b0), "r"(b1));
}
__device__ __forceinline__ void cp16(uint32_t dst, const void* src) {
    asm volatile("cp.async.cg.shared.global [%0], [%1], 16;"
                 :: "r"(dst), "l"(src) : "memory");
}
#define CP_COMMIT asm volatile("cp.async.commit_group;" ::: "memory")
#define CP_WAIT1  asm volatile("cp.async.wait_group 1;" ::: "memory")
#define CP_WAIT0  asm volatile("cp.async.wait_group 0;" ::: "memory")

__device__ __forceinline__ void split2(float x, float y, uint32_t& h, uint32_t& l) {
    __nv_bfloat16 hx = __float2bfloat16(x), hy = __float2bfloat16(y);
    __nv_bfloat16 lx = __float2bfloat16(x - __bfloat162float(hx));
    __nv_bfloat16 ly = __float2bfloat16(y - __bfloat162float(hy));
    h = ((uint32_t)__bfloat16_as_ushort(hy) << 16) | __bfloat16_as_ushort(hx);
    l = ((uint32_t)__bfloat16_as_ushort(ly) << 16) | __bfloat16_as_ushort(lx);
}

// ---------------------------------------------------------------------------
// One-shot fp32 -> split bf16 conversion: y=0..3: x segments, y=4..7: weights
// ---------------------------------------------------------------------------
#define NW4 (DMODEL * DMODEL / 4)   // 262144 float4 per weight / per x segment

__global__ void conv_all_kernel(const float* __restrict__ x,
                                const float* __restrict__ W0,
                                const float* __restrict__ W1,
                                const float* __restrict__ W2,
                                const float* __restrict__ W3,
                                __nv_bfloat16* __restrict__ xhi,
                                __nv_bfloat16* __restrict__ xlo,
                                __nv_bfloat16* __restrict__ whi,
                                __nv_bfloat16* __restrict__ wlo)
{
    const int i = blockIdx.x * blockDim.x + threadIdx.x;
    if (i >= NW4) return;
    const int y = blockIdx.y;
    const float* src;
    __nv_bfloat16 *dh, *dl;
    size_t off;
    if (y < 4) {
        src = x + (size_t)y * (NW4 * 4);
        dh = xhi; dl = xlo;
        off = (size_t)y * NW4 + i;
    } else {
        const int w = y - 4;
        src = (w == 0) ? W0 : (w == 1) ? W1 : (w == 2) ? W2 : W3;
        dh = whi; dl = wlo;
        off = (size_t)w * NW4 + i;
    }
    float4 v = ((const float4*)src)[i];
    uint32_t h0, l0, h1, l1;
    split2(v.x, v.y, h0, l0);
    split2(v.z, v.w, h1, l1);
    ((uint2*)dh)[off] = make_uint2(h0, h1);
    ((uint2*)dl)[off] = make_uint2(l0, l1);
}

// ---------------------------------------------------------------------------
// mma.sync bf16-split GEMM v3: C = A @ W^T + bias(segmented).
// 128x128 CTA tile, BK=32, 2-stage cp.async, 256 thr = 8 warps (4m x 2n).
// Inner loop: fragments loaded first, MMAs issued grouped by split term
// (8 independent accumulators between same-acc reuses).
// ---------------------------------------------------------------------------
#define GSLD 40
#define GT   10240
#define GSTAGE (4 * GT)
#define GSMEM (2 * GSTAGE)       // 81920 B

__global__ void __launch_bounds__(256, 2)
hmma_gemm_kernel(const __nv_bfloat16* __restrict__ Ahi,
                 const __nv_bfloat16* __restrict__ Alo,
                 const __nv_bfloat16* __restrict__ Whi,
                 const __nv_bfloat16* __restrict__ Wlo,
                 const float* __restrict__ b0,
                 const float* __restrict__ b1,
                 const float* __restrict__ b2,
                 float* __restrict__ Cf,
                 __nv_bfloat16* __restrict__ Chi,
                 __nv_bfloat16* __restrict__ Clo,
                 int M, int N, int K)
{
    extern __shared__ char smg[];
    const uint32_t sb = smem_u32(smg);

    const int tid = threadIdx.x;
    const int wid = tid >> 5;
    const int lane = tid & 31;
    const int warp_m = wid >> 1, warp_n = wid & 1;
    const int bm = blockIdx.y * 128;
    const int bn = blockIdx.x * 128;

    float acc[2][8][4];
#pragma unroll
    for (int i = 0; i < 2; i++)
#pragma unroll
        for (int j = 0; j < 8; j++)
#pragma unroll
            for (int e = 0; e < 4; e++) acc[i][j][e] = 0.0f;

    const int blk = lane >> 3, rr = lane & 7;
    const int a_m = (blk & 1) * 8 + rr, a_k = (blk >> 1) * 8;
    const int b_n = (blk >> 1) * 8 + rr, b_k = (blk & 1) * 8;

    const int crow = tid >> 1;
    const int cc = (tid & 1) * 2;

#define G_ISSUE(kc, buf)                                                      \
    do {                                                                      \
        const size_t ga = (size_t)(bm + crow) * K + (kc) * 32 + cc * 8;       \
        const size_t gw = (size_t)(bn + crow) * K + (kc) * 32 + cc * 8;       \
        const uint32_t s = sb + (buf) * GSTAGE;                               \
        const uint32_t ro = crow * 80 + cc * 16;                              \
        cp16(s + 0 * GT + ro,      Ahi + ga);                                 \
        cp16(s + 0 * GT + ro + 16, Ahi + ga + 8);                             \
        cp16(s + 1 * GT + ro,      Alo + ga);                                 \
        cp16(s + 1 * GT + ro + 16, Alo + ga + 8);                             \
        cp16(s + 2 * GT + ro,      Whi + gw);                                 \
        cp16(s + 2 * GT + ro + 16, Whi + gw + 8);                             \
        cp16(s + 3 * GT + ro,      Wlo + gw);                                 \
        cp16(s + 3 * GT + ro + 16, Wlo + gw + 8);                             \
    } while (0)

    G_ISSUE(0, 0);
    CP_COMMIT;

    const int nch = K / 32;
    for (int kc = 0; kc < nch; kc++) {
        if (kc + 1 < nch) {
            G_ISSUE(kc + 1, (kc + 1) & 1);
            CP_COMMIT;
            CP_WAIT1;
        } else {
            CP_WAIT0;
        }
        __syncthreads();

        const uint32_t s = sb + (kc & 1) * GSTAGE;
#pragma unroll
        for (int kk = 0; kk < 32; kk += 16) {
            uint32_t ah[2][4], al[2][4];
#pragma unroll
            for (int mt = 0; mt < 2; mt++) {
                uint32_t off = (uint32_t)((warp_m * 32 + mt * 16 + a_m) * GSLD
                                          + kk + a_k) * 2;
                ldsm_x4(ah[mt], s + 0 * GT + off);
                ldsm_x4(al[mt], s + 1 * GT + off);
            }
            // two nt2-groups of 2; within a group, MMAs issued term-major
            // across 8 independent accumulators.
#pragma unroll
            for (int grp = 0; grp < 2; grp++) {
                uint32_t bh[2][4], bl[2][4];
#pragma unroll
                for (int t2 = 0; t2 < 2; t2++) {
                    const int nt2 = grp * 2 + t2;
                    uint32_t off = (uint32_t)((warp_n * 64 + nt2 * 16 + b_n) * GSLD
                                              + kk + b_k) * 2;
                    ldsm_x4(bh[t2], s + 2 * GT + off);
                    ldsm_x4(bl[t2], s + 3 * GT + off);
                }
                // term 1: Ah * Wh
#pragma unroll
                for (int mt = 0; mt < 2; mt++)
#pragma unroll
                    for (int t2 = 0; t2 < 2; t2++)
#pragma unroll
                        for (int hf = 0; hf < 2; hf++)
                            mma16816(acc[mt][(grp * 2 + t2) * 2 + hf], ah[mt],
                                     bh[t2][hf * 2], bh[t2][hf * 2 + 1]);
                // term 2: Ah * Wl
#pragma unroll
                for (int mt = 0; mt < 2; mt++)
#pragma unroll
                    for (int t2 = 0; t2 < 2; t2++)
#pragma unroll
                        for (int hf = 0; hf < 2; hf++)
                            mma16816(acc[mt][(grp * 2 + t2) * 2 + hf], ah[mt],
                                     bl[t2][hf * 2], bl[t2][hf * 2 + 1]);
                // term 3: Al * Wh
#pragma unroll
                for (int mt = 0; mt < 2; mt++)
#pragma unroll
                    for (int t2 = 0; t2 < 2; t2++)
#pragma unroll
                        for (int hf = 0; hf < 2; hf++)
                            mma16816(acc[mt][(grp * 2 + t2) * 2 + hf], al[mt],
                                     bh[t2][hf * 2], bh[t2][hf * 2 + 1]);
            }
        }
        __syncthreads();
    }

    // ---- epilogue: segmented bias + store (fp32 or split-bf16) ----
    const int seg = bn >> 10;
    const float* bias = (seg == 0) ? b0 : (seg == 1) ? b1 : b2;
    const int boff = bn & 1023;
    const int g = lane >> 2, tig = lane & 3;
#pragma unroll
    for (int mt = 0; mt < 2; mt++) {
        const int row0 = bm + warp_m * 32 + mt * 16 + g;
#pragma unroll
        for (int nt = 0; nt < 8; nt++) {
            const int nl = warp_n * 64 + nt * 8 + tig * 2;
            const int n = bn + nl;
            const float bb0 = bias[boff + nl], bb1 = bias[boff + nl + 1];
            float c0 = acc[mt][nt][0] + bb0, c1 = acc[mt][nt][1] + bb1;
            float c2 = acc[mt][nt][2] + bb0, c3 = acc[mt][nt][3] + bb1;
            if (Cf) {
                *(float2*)&Cf[(size_t)row0 * N + n] = make_float2(c0, c1);
                *(float2*)&Cf[(size_t)(row0 + 8) * N + n] = make_float2(c2, c3);
            } else {
                uint32_t h, l;
                split2(c0, c1, h, l);
                *(uint32_t*)&Chi[(size_t)row0 * N + n] = h;
                *(uint32_t*)&Clo[(size_t)row0 * N + n] = l;
                split2(c2, c3, h, l);
                *(uint32_t*)&Chi[(size_t)(row0 + 8) * N + n] = h;
                *(uint32_t*)&Clo[(size_t)(row0 + 8) * N + n] = l;
            }
        }
    }
}

// ---------------------------------------------------------------------------
// Tensor-core flash attention. BQ=128 (8 warps), BKV=64, Dh=64.
// QKV read from fused buffer (row stride 3072, segments q|k|v).
// ---------------------------------------------------------------------------
#define SLD2 72
#define ATILE (64 * SLD2 * 2)
#define ABUF  (4 * ATILE)
#define ASMEM (2 * ABUF)

__global__ void __launch_bounds__(256, 1)
attn_mma_kernel(const __nv_bfloat16* __restrict__ qkvhi,
                const __nv_bfloat16* __restrict__ qkvlo,
                __nv_bfloat16* __restrict__ ahi,
                __nv_bfloat16* __restrict__ alo)
{
    extern __shared__ char smem[];
    const uint32_t sb = smem_u32(smem);

    const int tid = threadIdx.x;
    const int wid = tid >> 5;
    const int lane = tid & 31;
    const int b = blockIdx.z, h = blockIdx.y;
    const int q0 = blockIdx.x * 128;
    const size_t tokb = (size_t)b * SEQ;

    const int g = lane >> 2, tig = lane & 3;
    const int blk = lane >> 3, rr = lane & 7;
    const int a_m = (blk & 1) * 8 + rr, a_k = (blk >> 1) * 8;
    const int b_n = (blk >> 1) * 8 + rr, b_k = (blk & 1) * 8;

    // ---- stage Q tile (segment 0) ----
#pragma unroll
    for (int i = 0; i < 4; i++) {
        int slot = tid + 256 * i;
        int row = slot >> 3, c = slot & 7;
        size_t go = (tokb + q0 + row) * QKVD + h * HDIM + c * 8;
        *(uint4*)(smem + row * (SLD2 * 2) + c * 16) = *(const uint4*)(qkvhi + go);
        *(uint4*)(smem + 2 * ATILE + row * (SLD2 * 2) + c * 16) =
            *(const uint4*)(qkvlo + go);
    }
    __syncthreads();

    uint32_t qh[4][4], ql[4][4];
#pragma unroll
    for (int kk = 0; kk < 4; kk++) {
        uint32_t off = (uint32_t)((wid * 16 + a_m) * SLD2 + kk * 16 + a_k) * 2;
        ldsm_x4(qh[kk], sb + off);
        ldsm_x4(ql[kk], sb + 2 * ATILE + off);
    }
    __syncthreads();

    float oacc[8][4];
#pragma unroll
    for (int t = 0; t < 8; t++)
#pragma unroll
        for (int e = 0; e < 4; e++) oacc[t][e] = 0.0f;
    float mst0 = -1e30f, mst1 = -1e30f, lst0 = 0.0f, lst1 = 0.0f;

    // segments: K at +DMODEL, V at +2*DMODEL
    const __nv_bfloat16* kvp[4] = {qkvhi + DMODEL, qkvlo + DMODEL,
                                   qkvhi + 2 * DMODEL, qkvlo + 2 * DMODEL};
#define ISSUE_TILES(buf, kv0)                                                 \
    do {                                                                      \
        _Pragma("unroll")                                                     \
        for (int i = 0; i < 2; i++) {                                         \
            int slot = tid + 256 * i;                                         \
            int row = slot >> 3, c = slot & 7;                                \
            size_t go = (tokb + (kv0) + row) * QKVD + h * HDIM + c * 8;       \
            uint32_t so = sb + (buf) * ABUF + row * (SLD2 * 2) + c * 16;      \
            cp16(so + 0 * ATILE, kvp[0] + go);                                \
            cp16(so + 1 * ATILE, kvp[1] + go);                                \
            cp16(so + 2 * ATILE, kvp[2] + go);                                \
            cp16(so + 3 * ATILE, kvp[3] + go);                                \
        }                                                                     \
    } while (0)

    ISSUE_TILES(0, 0);
    CP_COMMIT;

    for (int kt = 0; kt < SEQ / 64; kt++) {
        if (kt + 1 < SEQ / 64) {
            ISSUE_TILES((kt + 1) & 1, (kt + 1) * 64);
            CP_COMMIT;
            CP_WAIT1;
        } else {
            CP_WAIT0;
        }
        __syncthreads();

        const uint32_t base = sb + (kt & 1) * ABUF;

        // ---- S = Q K^T (3-term split) ----
        float sacc[8][4];
#pragma unroll
        for (int t = 0; t < 8; t++)
#pragma unroll
            for (int e = 0; e < 4; e++) sacc[t][e] = 0.0f;

#pragma unroll
        for (int kk = 0; kk < 4; kk++) {
#pragma unroll
            for (int p = 0; p < 4; p++) {
                uint32_t bh[4], bl[4];
                uint32_t off = (uint32_t)((p * 16 + b_n) * SLD2 + kk * 16 + b_k) * 2;
                ldsm_x4(bh, base + 0 * ATILE + off);
                ldsm_x4(bl, base + 1 * ATILE + off);
                mma16816(sacc[2 * p],     qh[kk], bh[0], bh[1]);
                mma16816(sacc[2 * p],     qh[kk], bl[0], bl[1]);
                mma16816(sacc[2 * p],     ql[kk], bh[0], bh[1]);
                mma16816(sacc[2 * p + 1], qh[kk], bh[2], bh[3]);
                mma16816(sacc[2 * p + 1], qh[kk], bl[2], bl[3]);
                mma16816(sacc[2 * p + 1], ql[kk], bh[2], bh[3]);
            }
        }

        // ---- online softmax ----
#pragma unroll
        for (int t = 0; t < 8; t++)
#pragma unroll
            for (int e = 0; e < 4; e++) sacc[t][e] *= 0.125f;

        float rm0 = -1e30f, rm1 = -1e30f;
#pragma unroll
        for (int t = 0; t < 8; t++) {
            rm0 = fmaxf(rm0, fmaxf(sacc[t][0], sacc[t][1]));
            rm1 = fmaxf(rm1, fmaxf(sacc[t][2], sacc[t][3]));
        }
        rm0 = fmaxf(rm0, __shfl_xor_sync(0xffffffffu, rm0, 1));
        rm0 = fmaxf(rm0, __shfl_xor_sync(0xffffffffu, rm0, 2));
        rm1 = fmaxf(rm1, __shfl_xor_sync(0xffffffffu, rm1, 1));
        rm1 = fmaxf(rm1, __shfl_xor_sync(0xffffffffu, rm1, 2));

        const float mn0 = fmaxf(mst0, rm0), mn1 = fmaxf(mst1, rm1);
        const float co0 = __expf(mst0 - mn0), co1 = __expf(mst1 - mn1);
        mst0 = mn0; mst1 = mn1;

        float sum0 = 0.0f, sum1 = 0.0f;
#pragma unroll
        for (int t = 0; t < 8; t++) {
            sacc[t][0] = __expf(sacc[t][0] - mn0); sum0 += sacc[t][0];
            sacc[t][1] = __expf(sacc[t][1] - mn0); sum0 += sacc[t][1];
            sacc[t][2] = __expf(sacc[t][2] - mn1); sum1 += sacc[t][2];
            sacc[t][3] = __expf(sacc[t][3] - mn1); sum1 += sacc[t][3];
        }
        sum0 += __shfl_xor_sync(0xffffffffu, sum0, 1);
        sum0 += __shfl_xor_sync(0xffffffffu, sum0, 2);
        sum1 += __shfl_xor_sync(0xffffffffu, sum1, 1);
        sum1 += __shfl_xor_sync(0xffffffffu, sum1, 2);
        lst0 = lst0 * co0 + sum0;
        lst1 = lst1 * co1 + sum1;

#pragma unroll
        for (int t = 0; t < 8; t++) {
            oacc[t][0] *= co0; oacc[t][1] *= co0;
            oacc[t][2] *= co1; oacc[t][3] *= co1;
        }

        // ---- pack P (acc layout == A-fragment layout) ----
        uint32_t ph[4][4], pl[4][4];
#pragma unroll
        for (int j = 0; j < 4; j++) {
            const int t0 = 2 * j, t1 = 2 * j + 1;
            split2(sacc[t0][0], sacc[t0][1], ph[j][0], pl[j][0]);
            split2(sacc[t0][2], sacc[t0][3], ph[j][1], pl[j][1]);
            split2(sacc[t1][0], sacc[t1][1], ph[j][2], pl[j][2]);
            split2(sacc[t1][2], sacc[t1][3], ph[j][3], pl[j][3]);
        }

        // ---- O += P V (3-term split; V via ldmatrix.trans) ----
#pragma unroll
        for (int kk = 0; kk < 4; kk++) {
#pragma unroll
            for (int p = 0; p < 4; p++) {
                uint32_t bh[4], bl[4];
                uint32_t off = (uint32_t)((kk * 16 + a_m) * SLD2 + p * 16 + a_k) * 2;
                ldsm_x4_t(bh, base + 2 * ATILE + off);
                ldsm_x4_t(bl, base + 3 * ATILE + off);
                mma16816(oacc[2 * p],     ph[kk], bh[0], bh[1]);
                mma16816(oacc[2 * p],     ph[kk], bl[0], bl[1]);
                mma16816(oacc[2 * p],     pl[kk], bh[0], bh[1]);
                mma16816(oacc[2 * p + 1], ph[kk], bh[2], bh[3]);
                mma16816(oacc[2 * p + 1], ph[kk], bl[2], bl[3]);
                mma16816(oacc[2 * p + 1], pl[kk], bh[2], bh[3]);
            }
        }
        __syncthreads();
    }

    // ---- epilogue: normalize, emit split-bf16 ----
    const float inv0 = 1.0f / lst0, inv1 = 1.0f / lst1;
    const size_t base0 = (tokb + q0 + wid * 16 + g) * DMODEL + h * HDIM;
#pragma unroll
    for (int t = 0; t < 8; t++) {
        const int cc2 = t * 8 + tig * 2;
        uint32_t hh, ll;
        split2(oacc[t][0] * inv0, oacc[t][1] * inv0, hh, ll);
        *(uint32_t*)&ahi[base0 + cc2] = hh;
        *(uint32_t*)&alo[base0 + cc2] = ll;
        split2(oacc[t][2] * inv1, oacc[t][3] * inv1, hh, ll);
        *(uint32_t*)&ahi[base0 + 8 * DMODEL + cc2] = hh;
        *(uint32_t*)&alo[base0 + 8 * DMODEL + cc2] = ll;
    }
}

// ---------------------------------------------------------------------------
// Launch
// ---------------------------------------------------------------------------
extern "C" void kernel_launch(void* const* d_in, const int* in_sizes, int n_in,
                              void* d_out, int out_size)
{
    const float* x  = (const float*)d_in[0];
    const float* Wq = (const float*)d_in[1];
    const float* bq = (const float*)d_in[2];
    const float* Wk = (const float*)d_in[3];
    const float* bk = (const float*)d_in[4];
    const float* Wv = (const float*)d_in[5];
    const float* bv = (const float*)d_in[6];
    const float* Wo = (const float*)d_in[7];
    const float* bo = (const float*)d_in[8];
    float* out = (float*)d_out;

    __nv_bfloat16 *xhi, *xlo, *qkvhi, *qkvlo, *ahi, *alo, *whi, *wlo;
    cudaGetSymbolAddress((void**)&xhi, g_xhi);
    cudaGetSymbolAddress((void**)&xlo, g_xlo);
    cudaGetSymbolAddress((void**)&qkvhi, g_qkvhi);
    cudaGetSymbolAddress((void**)&qkvlo, g_qkvlo);
    cudaGetSymbolAddress((void**)&ahi, g_ahi);
    cudaGetSymbolAddress((void**)&alo, g_alo);
    cudaGetSymbolAddress((void**)&whi, g_whi);
    cudaGetSymbolAddress((void**)&wlo, g_wlo);

    cudaFuncSetAttribute(hmma_gemm_kernel,
                         cudaFuncAttributeMaxDynamicSharedMemorySize, GSMEM);
    cudaFuncSetAttribute(attn_mma_kernel,
                         cudaFuncAttributeMaxDynamicSharedMemorySize, ASMEM);

    const int WSZ = DMODEL * DMODEL;

    // conversions: one launch (x in 4 segments + 4 weights)
    dim3 cgrid((NW4 + 255) / 256, 8);
    conv_all_kernel<<<cgrid, 256>>>(x, Wq, Wk, Wv, Wo, xhi, xlo, whi, wlo);

    // fused QKV projection: N = 3072 against stacked weights
    dim3 qkvgrid(QKVD / 128, MROWS / 128);  // (24, 32) = 768 CTAs
    hmma_gemm_kernel<<<qkvgrid, 256, GSMEM>>>(xhi, xlo, whi, wlo,
                                              bq, bk, bv,
                                              nullptr, qkvhi, qkvlo,
                                              MROWS, QKVD, DMODEL);

    dim3 agrid(SEQ / 128, NHEADS, BATCH);   // (16, 16, 2)
    attn_mma_kernel<<<agrid, 256, ASMEM>>>(qkvhi, qkvlo, ahi, alo);

    // output projection: N = 1024
    dim3 ogrid(DMODEL / 128, MROWS / 128);  // (8, 32)
    hmma_gemm_kernel<<<ogrid, 256, GSMEM>>>(ahi, alo, whi + 3 * WSZ, wlo + 3 * WSZ,
                                            bo, bo, bo,
                                            out, nullptr, nullptr,
                                            MROWS, DMODEL, DMODEL);
}

// round 8
// speedup vs baseline: 4.7448x; 1.0509x over previous
#include <cuda_runtime.h>
#include <cuda_bf16.h>
#include <cstdint>
#include <math.h>

// ---------------------------------------------------------------------------
// StandardAttention on GB300 (sm_103 mma.sync HMMA path)
// B=2, S=2048, D=1024, H=16, Dh=64, fp32 io.
// R7: GEMM v4 — 128x256 CTA tile, 64x64 warp tiles (half the smem bytes per
//     MMA), 3-stage cp.async. Attention unchanged. Split-bf16 3-term.
// ---------------------------------------------------------------------------

#define BATCH 2
#define SEQ   2048
#define DMODEL 1024
#define NHEADS 16
#define HDIM  64
#define MROWS (BATCH * SEQ)   // 4096
#define QKVD  (3 * DMODEL)    // 3072

// ---------------- scratch (__device__ globals) -----------------------------
__device__ __align__(16) __nv_bfloat16 g_xhi[MROWS * DMODEL];
__device__ __align__(16) __nv_bfloat16 g_xlo[MROWS * DMODEL];
__device__ __align__(16) __nv_bfloat16 g_qkvhi[MROWS * QKVD];
__device__ __align__(16) __nv_bfloat16 g_qkvlo[MROWS * QKVD];
__device__ __align__(16) __nv_bfloat16 g_ahi[MROWS * DMODEL];
__device__ __align__(16) __nv_bfloat16 g_alo[MROWS * DMODEL];
__device__ __align__(16) __nv_bfloat16 g_whi[4][DMODEL * DMODEL];
__device__ __align__(16) __nv_bfloat16 g_wlo[4][DMODEL * DMODEL];

// ---------------- small helpers --------------------------------------------
__device__ __forceinline__ uint32_t smem_u32(const void* p) {
    uint32_t a;
    asm("{ .reg .u64 t; cvta.to.shared.u64 t, %1; cvt.u32.u64 %0, t; }"
        : "=r"(a) : "l"(p));
    return a;
}
__device__ __forceinline__ void ldsm_x4(uint32_t* r, uint32_t addr) {
    asm volatile("ldmatrix.sync.aligned.m8n8.x4.shared.b16 {%0,%1,%2,%3}, [%4];"
                 : "=r"(r[0]), "=r"(r[1]), "=r"(r[2]), "=r"(r[3]) : "r"(addr));
}
__device__ __forceinline__ void ldsm_x4_t(uint32_t* r, uint32_t addr) {
    asm volatile("ldmatrix.sync.aligned.m8n8.x4.trans.shared.b16 {%0,%1,%2,%3}, [%4];"
                 : "=r"(r[0]), "=r"(r[1]), "=r"(r[2]), "=r"(r[3]) : "r"(addr));
}
__device__ __forceinline__ void mma16816(float* d, const uint32_t* a,
                                         uint32_t b0, uint32_t b1) {
    asm volatile(
        "mma.sync.aligned.m16n8k16.row.col.f32.bf16.bf16.f32 "
        "{%0,%1,%2,%3}, {%4,%5,%6,%7}, {%8,%9}, {%0,%1,%2,%3};"
        : "+f"(d[0]), "+f"(d[1]), "+f"(d[2]), "+f"(d[3])
        : "r"(a[0]), "r"(a[1]), "r"(a[2]), "r"(a[3]), "r"(b0), "r"(b1));
}
__device__ __forceinline__ void cp16(uint32_t dst, const void* src) {
    asm volatile("cp.async.cg.shared.global [%0], [%1], 16;"
                 :: "r"(dst), "l"(src) : "memory");
}
#define CP_COMMIT asm volatile("cp.async.commit_group;" ::: "memory")
#define CP_WAIT1  asm volatile("cp.async.wait_group 1;" ::: "memory")
#define CP_WAIT0  asm volatile("cp.async.wait_group 0;" ::: "memory")

__device__ __forceinline__ void split2(float x, float y, uint32_t& h, uint32_t& l) {
    __nv_bfloat16 hx = __float2bfloat16(x), hy = __float2bfloat16(y);
    __nv_bfloat16 lx = __float2bfloat16(x - __bfloat162float(hx));
    __nv_bfloat16 ly = __float2bfloat16(y - __bfloat162float(hy));
    h = ((uint32_t)__bfloat16_as_ushort(hy) << 16) | __bfloat16_as_ushort(hx);
    l = ((uint32_t)__bfloat16_as_ushort(ly) << 16) | __bfloat16_as_ushort(lx);
}

// ---------------------------------------------------------------------------
// One-shot fp32 -> split bf16 conversion: y=0..3: x segments, y=4..7: weights
// ---------------------------------------------------------------------------
#define NW4 (DMODEL * DMODEL / 4)

__global__ void conv_all_kernel(const float* __restrict__ x,
                                const float* __restrict__ W0,
                                const float* __restrict__ W1,
                                const float* __restrict__ W2,
                                const float* __restrict__ W3,
                                __nv_bfloat16* __restrict__ xhi,
                                __nv_bfloat16* __restrict__ xlo,
                                __nv_bfloat16* __restrict__ whi,
                                __nv_bfloat16* __restrict__ wlo)
{
    const int i = blockIdx.x * blockDim.x + threadIdx.x;
    if (i >= NW4) return;
    const int y = blockIdx.y;
    const float* src;
    __nv_bfloat16 *dh, *dl;
    size_t off;
    if (y < 4) {
        src = x + (size_t)y * (NW4 * 4);
        dh = xhi; dl = xlo;
        off = (size_t)y * NW4 + i;
    } else {
        const int w = y - 4;
        src = (w == 0) ? W0 : (w == 1) ? W1 : (w == 2) ? W2 : W3;
        dh = whi; dl = wlo;
        off = (size_t)w * NW4 + i;
    }
    float4 v = ((const float4*)src)[i];
    uint32_t h0, l0, h1, l1;
    split2(v.x, v.y, h0, l0);
    split2(v.z, v.w, h1, l1);
    ((uint2*)dh)[off] = make_uint2(h0, h1);
    ((uint2*)dl)[off] = make_uint2(l0, l1);
}

// ---------------------------------------------------------------------------
// mma.sync bf16-split GEMM v4: C = A @ W^T + bias(segmented).
// CTA 128(M) x 256(N), BK=32, 3-stage cp.async, 256 thr = 8 warps (2m x 4n),
// warp tile 64x64 -> 16 ldsm per 96 MMAs per kk.
// ---------------------------------------------------------------------------
#define GSLD 40                   // padded row: 40 bf16 = 80 B
#define OFF_AH 0
#define OFF_AL 10240
#define OFF_WH 20480
#define OFF_WL 40960
#define GSTAGE 61440              // Ah(10240)+Al(10240)+Wh(20480)+Wl(20480)
#define GSMEM (3 * GSTAGE)        // 184320 B

__global__ void __launch_bounds__(256, 1)
hmma_gemm_kernel(const __nv_bfloat16* __restrict__ Ahi,
                 const __nv_bfloat16* __restrict__ Alo,
                 const __nv_bfloat16* __restrict__ Whi,
                 const __nv_bfloat16* __restrict__ Wlo,
                 const float* __restrict__ b0,
                 const float* __restrict__ b1,
                 const float* __restrict__ b2,
                 float* __restrict__ Cf,
                 __nv_bfloat16* __restrict__ Chi,
                 __nv_bfloat16* __restrict__ Clo,
                 int M, int N, int K)
{
    extern __shared__ char smg[];
    const uint32_t sb = smem_u32(smg);

    const int tid = threadIdx.x;
    const int wid = tid >> 5;
    const int lane = tid & 31;
    const int warp_m = wid & 1;        // 2 m-warps of 64 rows
    const int warp_n = wid >> 1;       // 4 n-warps of 64 cols
    const int bm = blockIdx.y * 128;
    const int bn = blockIdx.x * 256;

    float acc[4][8][4];
#pragma unroll
    for (int i = 0; i < 4; i++)
#pragma unroll
        for (int j = 0; j < 8; j++)
#pragma unroll
            for (int e = 0; e < 4; e++) acc[i][j][e] = 0.0f;

    const int blk = lane >> 3, rr = lane & 7;
    const int a_m = (blk & 1) * 8 + rr, a_k = (blk >> 1) * 8;
    const int b_n = (blk >> 1) * 8 + rr, b_k = (blk & 1) * 8;

#define G_ISSUE(kc, buf)                                                      \
    do {                                                                      \
        const uint32_t s = sb + (buf) * GSTAGE;                               \
        _Pragma("unroll")                                                     \
        for (int i = 0; i < 2; i++) {    /* A: 128 rows x 4 c16 (h+l) */      \
            int slot = tid + 256 * i;                                         \
            int row = slot >> 2, c16 = slot & 3;                              \
            const size_t ga = (size_t)(bm + row) * K + (kc) * 32 + c16 * 8;   \
            const uint32_t ro = row * 80 + c16 * 16;                          \
            cp16(s + OFF_AH + ro, Ahi + ga);                                  \
            cp16(s + OFF_AL + ro, Alo + ga);                                  \
        }                                                                     \
        _Pragma("unroll")                                                     \
        for (int i = 0; i < 4; i++) {    /* W: 256 rows x 4 c16 (h+l) */      \
            int slot = tid + 256 * i;                                         \
            int row = slot >> 2, c16 = slot & 3;                              \
            const size_t gw = (size_t)(bn + row) * K + (kc) * 32 + c16 * 8;   \
            const uint32_t ro = row * 80 + c16 * 16;                          \
            cp16(s + OFF_WH + ro, Whi + gw);                                  \
            cp16(s + OFF_WL + ro, Wlo + gw);                                  \
        }                                                                     \
    } while (0)

    const int nch = K / 32;
    G_ISSUE(0, 0);
    CP_COMMIT;
    G_ISSUE(1, 1);
    CP_COMMIT;

    int buf = 0;
    for (int kc = 0; kc < nch; kc++) {
        if (kc + 1 < nch) { CP_WAIT1; } else { CP_WAIT0; }
        __syncthreads();
        // refill the buffer freed by chunk kc-1
        if (kc + 2 < nch) {
            int nb = buf + 2; if (nb >= 3) nb -= 3;
            G_ISSUE(kc + 2, nb);
            CP_COMMIT;
        }

        const uint32_t s = sb + buf * GSTAGE;
#pragma unroll
        for (int kk = 0; kk < 32; kk += 16) {
            uint32_t ah[4][4], al[4][4];
#pragma unroll
            for (int mt = 0; mt < 4; mt++) {
                uint32_t off = (uint32_t)((warp_m * 64 + mt * 16 + a_m) * GSLD
                                          + kk + a_k) * 2;
                ldsm_x4(ah[mt], s + OFF_AH + off);
                ldsm_x4(al[mt], s + OFF_AL + off);
            }
#pragma unroll
            for (int nt2 = 0; nt2 < 4; nt2++) {
                uint32_t bh[4], bl[4];
                uint32_t off = (uint32_t)((warp_n * 64 + nt2 * 16 + b_n) * GSLD
                                          + kk + b_k) * 2;
                ldsm_x4(bh, s + OFF_WH + off);
                ldsm_x4(bl, s + OFF_WL + off);
                // term-major issue: 8 independent accs between same-acc reuse
#pragma unroll
                for (int mt = 0; mt < 4; mt++)
#pragma unroll
                    for (int hf = 0; hf < 2; hf++)
                        mma16816(acc[mt][nt2 * 2 + hf], ah[mt],
                                 bh[hf * 2], bh[hf * 2 + 1]);
#pragma unroll
                for (int mt = 0; mt < 4; mt++)
#pragma unroll
                    for (int hf = 0; hf < 2; hf++)
                        mma16816(acc[mt][nt2 * 2 + hf], ah[mt],
                                 bl[hf * 2], bl[hf * 2 + 1]);
#pragma unroll
                for (int mt = 0; mt < 4; mt++)
#pragma unroll
                    for (int hf = 0; hf < 2; hf++)
                        mma16816(acc[mt][nt2 * 2 + hf], al[mt],
                                 bh[hf * 2], bh[hf * 2 + 1]);
            }
        }
        __syncthreads();
        buf++; if (buf >= 3) buf = 0;
    }

    // ---- epilogue: segmented bias + store ----
    const int g = lane >> 2, tig = lane & 3;
#pragma unroll
    for (int mt = 0; mt < 4; mt++) {
        const int row0 = bm + warp_m * 64 + mt * 16 + g;
#pragma unroll
        for (int nt = 0; nt < 8; nt++) {
            const int nl = warp_n * 64 + nt * 8 + tig * 2;
            const int n = bn + nl;
            const int seg = n >> 10;
            const float* bias = (seg == 0) ? b0 : (seg == 1) ? b1 : b2;
            const int nb = n & 1023;
            const float bb0 = bias[nb], bb1 = bias[nb + 1];
            float c0 = acc[mt][nt][0] + bb0, c1 = acc[mt][nt][1] + bb1;
            float c2 = acc[mt][nt][2] + bb0, c3 = acc[mt][nt][3] + bb1;
            if (Cf) {
                *(float2*)&Cf[(size_t)row0 * N + n] = make_float2(c0, c1);
                *(float2*)&Cf[(size_t)(row0 + 8) * N + n] = make_float2(c2, c3);
            } else {
                uint32_t h, l;
                split2(c0, c1, h, l);
                *(uint32_t*)&Chi[(size_t)row0 * N + n] = h;
                *(uint32_t*)&Clo[(size_t)row0 * N + n] = l;
                split2(c2, c3, h, l);
                *(uint32_t*)&Chi[(size_t)(row0 + 8) * N + n] = h;
                *(uint32_t*)&Clo[(size_t)(row0 + 8) * N + n] = l;
            }
        }
    }
}

// ---------------------------------------------------------------------------
// Tensor-core flash attention (unchanged from R6). BQ=128, BKV=64, Dh=64.
// ---------------------------------------------------------------------------
#define SLD2 72
#define ATILE (64 * SLD2 * 2)
#define ABUF  (4 * ATILE)
#define ASMEM (2 * ABUF)

__global__ void __launch_bounds__(256, 1)
attn_mma_kernel(const __nv_bfloat16* __restrict__ qkvhi,
                const __nv_bfloat16* __restrict__ qkvlo,
                __nv_bfloat16* __restrict__ ahi,
                __nv_bfloat16* __restrict__ alo)
{
    extern __shared__ char smem[];
    const uint32_t sb = smem_u32(smem);

    const int tid = threadIdx.x;
    const int wid = tid >> 5;
    const int lane = tid & 31;
    const int b = blockIdx.z, h = blockIdx.y;
    const int q0 = blockIdx.x * 128;
    const size_t tokb = (size_t)b * SEQ;

    const int g = lane >> 2, tig = lane & 3;
    const int blk = lane >> 3, rr = lane & 7;
    const int a_m = (blk & 1) * 8 + rr, a_k = (blk >> 1) * 8;
    const int b_n = (blk >> 1) * 8 + rr, b_k = (blk & 1) * 8;

#pragma unroll
    for (int i = 0; i < 4; i++) {
        int slot = tid + 256 * i;
        int row = slot >> 3, c = slot & 7;
        size_t go = (tokb + q0 + row) * QKVD + h * HDIM + c * 8;
        *(uint4*)(smem + row * (SLD2 * 2) + c * 16) = *(const uint4*)(qkvhi + go);
        *(uint4*)(smem + 2 * ATILE + row * (SLD2 * 2) + c * 16) =
            *(const uint4*)(qkvlo + go);
    }
    __syncthreads();

    uint32_t qh[4][4], ql[4][4];
#pragma unroll
    for (int kk = 0; kk < 4; kk++) {
        uint32_t off = (uint32_t)((wid * 16 + a_m) * SLD2 + kk * 16 + a_k) * 2;
        ldsm_x4(qh[kk], sb + off);
        ldsm_x4(ql[kk], sb + 2 * ATILE + off);
    }
    __syncthreads();

    float oacc[8][4];
#pragma unroll
    for (int t = 0; t < 8; t++)
#pragma unroll
        for (int e = 0; e < 4; e++) oacc[t][e] = 0.0f;
    float mst0 = -1e30f, mst1 = -1e30f, lst0 = 0.0f, lst1 = 0.0f;

    const __nv_bfloat16* kvp[4] = {qkvhi + DMODEL, qkvlo + DMODEL,
                                   qkvhi + 2 * DMODEL, qkvlo + 2 * DMODEL};
#define ISSUE_TILES(buf, kv0)                                                 \
    do {                                                                      \
        _Pragma("unroll")                                                     \
        for (int i = 0; i < 2; i++) {                                         \
            int slot = tid + 256 * i;                                         \
            int row = slot >> 3, c = slot & 7;                                \
            size_t go = (tokb + (kv0) + row) * QKVD + h * HDIM + c * 8;       \
            uint32_t so = sb + (buf) * ABUF + row * (SLD2 * 2) + c * 16;      \
            cp16(so + 0 * ATILE, kvp[0] + go);                                \
            cp16(so + 1 * ATILE, kvp[1] + go);                                \
            cp16(so + 2 * ATILE, kvp[2] + go);                                \
            cp16(so + 3 * ATILE, kvp[3] + go);                                \
        }                                                                     \
    } while (0)

    ISSUE_TILES(0, 0);
    CP_COMMIT;

    for (int kt = 0; kt < SEQ / 64; kt++) {
        if (kt + 1 < SEQ / 64) {
            ISSUE_TILES((kt + 1) & 1, (kt + 1) * 64);
            CP_COMMIT;
            CP_WAIT1;
        } else {
            CP_WAIT0;
        }
        __syncthreads();

        const uint32_t base = sb + (kt & 1) * ABUF;

        float sacc[8][4];
#pragma unroll
        for (int t = 0; t < 8; t++)
#pragma unroll
            for (int e = 0; e < 4; e++) sacc[t][e] = 0.0f;

#pragma unroll
        for (int kk = 0; kk < 4; kk++) {
#pragma unroll
            for (int p = 0; p < 4; p++) {
                uint32_t bh[4], bl[4];
                uint32_t off = (uint32_t)((p * 16 + b_n) * SLD2 + kk * 16 + b_k) * 2;
                ldsm_x4(bh, base + 0 * ATILE + off);
                ldsm_x4(bl, base + 1 * ATILE + off);
                mma16816(sacc[2 * p],     qh[kk], bh[0], bh[1]);
                mma16816(sacc[2 * p],     qh[kk], bl[0], bl[1]);
                mma16816(sacc[2 * p],     ql[kk], bh[0], bh[1]);
                mma16816(sacc[2 * p + 1], qh[kk], bh[2], bh[3]);
                mma16816(sacc[2 * p + 1], qh[kk], bl[2], bl[3]);
                mma16816(sacc[2 * p + 1], ql[kk], bh[2], bh[3]);
            }
        }

#pragma unroll
        for (int t = 0; t < 8; t++)
#pragma unroll
            for (int e = 0; e < 4; e++) sacc[t][e] *= 0.125f;

        float rm0 = -1e30f, rm1 = -1e30f;
#pragma unroll
        for (int t = 0; t < 8; t++) {
            rm0 = fmaxf(rm0, fmaxf(sacc[t][0], sacc[t][1]));
            rm1 = fmaxf(rm1, fmaxf(sacc[t][2], sacc[t][3]));
        }
        rm0 = fmaxf(rm0, __shfl_xor_sync(0xffffffffu, rm0, 1));
        rm0 = fmaxf(rm0, __shfl_xor_sync(0xffffffffu, rm0, 2));
        rm1 = fmaxf(rm1, __shfl_xor_sync(0xffffffffu, rm1, 1));
        rm1 = fmaxf(rm1, __shfl_xor_sync(0xffffffffu, rm1, 2));

        const float mn0 = fmaxf(mst0, rm0), mn1 = fmaxf(mst1, rm1);
        const float co0 = __expf(mst0 - mn0), co1 = __expf(mst1 - mn1);
        mst0 = mn0; mst1 = mn1;

        float sum0 = 0.0f, sum1 = 0.0f;
#pragma unroll
        for (int t = 0; t < 8; t++) {
            sacc[t][0] = __expf(sacc[t][0] - mn0); sum0 += sacc[t][0];
            sacc[t][1] = __expf(sacc[t][1] - mn0); sum0 += sacc[t][1];
            sacc[t][2] = __expf(sacc[t][2] - mn1); sum1 += sacc[t][2];
            sacc[t][3] = __expf(sacc[t][3] - mn1); sum1 += sacc[t][3];
        }
        sum0 += __shfl_xor_sync(0xffffffffu, sum0, 1);
        sum0 += __shfl_xor_sync(0xffffffffu, sum0, 2);
        sum1 += __shfl_xor_sync(0xffffffffu, sum1, 1);
        sum1 += __shfl_xor_sync(0xffffffffu, sum1, 2);
        lst0 = lst0 * co0 + sum0;
        lst1 = lst1 * co1 + sum1;

#pragma unroll
        for (int t = 0; t < 8; t++) {
            oacc[t][0] *= co0; oacc[t][1] *= co0;
            oacc[t][2] *= co1; oacc[t][3] *= co1;
        }

        uint32_t ph[4][4], pl[4][4];
#pragma unroll
        for (int j = 0; j < 4; j++) {
            const int t0 = 2 * j, t1 = 2 * j + 1;
            split2(sacc[t0][0], sacc[t0][1], ph[j][0], pl[j][0]);
            split2(sacc[t0][2], sacc[t0][3], ph[j][1], pl[j][1]);
            split2(sacc[t1][0], sacc[t1][1], ph[j][2], pl[j][2]);
            split2(sacc[t1][2], sacc[t1][3], ph[j][3], pl[j][3]);
        }

#pragma unroll
        for (int kk = 0; kk < 4; kk++) {
#pragma unroll
            for (int p = 0; p < 4; p++) {
                uint32_t bh[4], bl[4];
                uint32_t off = (uint32_t)((kk * 16 + a_m) * SLD2 + p * 16 + a_k) * 2;
                ldsm_x4_t(bh, base + 2 * ATILE + off);
                ldsm_x4_t(bl, base + 3 * ATILE + off);
                mma16816(oacc[2 * p],     ph[kk], bh[0], bh[1]);
                mma16816(oacc[2 * p],     ph[kk], bl[0], bl[1]);
                mma16816(oacc[2 * p],     pl[kk], bh[0], bh[1]);
                mma16816(oacc[2 * p + 1], ph[kk], bh[2], bh[3]);
                mma16816(oacc[2 * p + 1], ph[kk], bl[2], bl[3]);
                mma16816(oacc[2 * p + 1], pl[kk], bh[2], bh[3]);
            }
        }
        __syncthreads();
    }

    const float inv0 = 1.0f / lst0, inv1 = 1.0f / lst1;
    const size_t base0 = (tokb + q0 + wid * 16 + g) * DMODEL + h * HDIM;
#pragma unroll
    for (int t = 0; t < 8; t++) {
        const int cc2 = t * 8 + tig * 2;
        uint32_t hh, ll;
        split2(oacc[t][0] * inv0, oacc[t][1] * inv0, hh, ll);
        *(uint32_t*)&ahi[base0 + cc2] = hh;
        *(uint32_t*)&alo[base0 + cc2] = ll;
        split2(oacc[t][2] * inv1, oacc[t][3] * inv1, hh, ll);
        *(uint32_t*)&ahi[base0 + 8 * DMODEL + cc2] = hh;
        *(uint32_t*)&alo[base0 + 8 * DMODEL + cc2] = ll;
    }
}

// ---------------------------------------------------------------------------
// Launch
// ---------------------------------------------------------------------------
extern "C" void kernel_launch(void* const* d_in, const int* in_sizes, int n_in,
                              void* d_out, int out_size)
{
    const float* x  = (const float*)d_in[0];
    const float* Wq = (const float*)d_in[1];
    const float* bq = (const float*)d_in[2];
    const float* Wk = (const float*)d_in[3];
    const float* bk = (const float*)d_in[4];
    const float* Wv = (const float*)d_in[5];
    const float* bv = (const float*)d_in[6];
    const float* Wo = (const float*)d_in[7];
    const float* bo = (const float*)d_in[8];
    float* out = (float*)d_out;

    __nv_bfloat16 *xhi, *xlo, *qkvhi, *qkvlo, *ahi, *alo, *whi, *wlo;
    cudaGetSymbolAddress((void**)&xhi, g_xhi);
    cudaGetSymbolAddress((void**)&xlo, g_xlo);
    cudaGetSymbolAddress((void**)&qkvhi, g_qkvhi);
    cudaGetSymbolAddress((void**)&qkvlo, g_qkvlo);
    cudaGetSymbolAddress((void**)&ahi, g_ahi);
    cudaGetSymbolAddress((void**)&alo, g_alo);
    cudaGetSymbolAddress((void**)&whi, g_whi);
    cudaGetSymbolAddress((void**)&wlo, g_wlo);

    cudaFuncSetAttribute(hmma_gemm_kernel,
                         cudaFuncAttributeMaxDynamicSharedMemorySize, GSMEM);
    cudaFuncSetAttribute(attn_mma_kernel,
                         cudaFuncAttributeMaxDynamicSharedMemorySize, ASMEM);

    const int WSZ = DMODEL * DMODEL;

    dim3 cgrid((NW4 + 255) / 256, 8);
    conv_all_kernel<<<cgrid, 256>>>(x, Wq, Wk, Wv, Wo, xhi, xlo, whi, wlo);

    // fused QKV projection: N = 3072
    dim3 qkvgrid(QKVD / 256, MROWS / 128);  // (12, 32) = 384 CTAs
    hmma_gemm_kernel<<<qkvgrid, 256, GSMEM>>>(xhi, xlo, whi, wlo,
                                              bq, bk, bv,
                                              nullptr, qkvhi, qkvlo,
                                              MROWS, QKVD, DMODEL);

    dim3 agrid(SEQ / 128, NHEADS, BATCH);   // (16, 16, 2)
    attn_mma_kernel<<<agrid, 256, ASMEM>>>(qkvhi, qkvlo, ahi, alo);

    // output projection: N = 1024
    dim3 ogrid(DMODEL / 256, MROWS / 128);  // (4, 32) = 128 CTAs
    hmma_gemm_kernel<<<ogrid, 256, GSMEM>>>(ahi, alo, whi + 3 * WSZ, wlo + 3 * WSZ,
                                            bo, bo, bo,
                                            out, nullptr, nullptr,
                                            MROWS, DMODEL, DMODEL);
}